// round 3
// baseline (speedup 1.0000x reference)
#include <cuda_runtime.h>
#include <mma.h>
#include <math.h>

using namespace nvcuda;

// Problem constants
#define BB 4
#define SEQ 2048
#define EMB 1024
#define NH 16
#define HD 64

// Scratch (device globals — no allocations allowed)
__device__ float g_q[BB * NH * SEQ * HD];
__device__ float g_k[BB * NH * SEQ * HD];
__device__ float g_v[BB * NH * SEQ * HD];
__device__ float g_attn[BB * SEQ * EMB];

template <class Frag>
__device__ __forceinline__ void frag_to_tf32(Frag& f) {
#pragma unroll
    for (int t = 0; t < f.num_elements; t++) f.x[t] = wmma::__float_to_tf32(f.x[t]);
}

// ---------------------------------------------------------------------------
// TF32 GEMM: C[8192 x N] = A[8192 x 1024] @ B[1024 x N] + bias
//  mode 0: A = x, epilogue scatters into g_q/g_k/g_v ([B,H,S,D] layout)
//  mode 1: A = g_attn, epilogue writes out[m*1024 + c]
// BM=128, BN=64, BK=32, 256 threads, warp grid 4x2, warp tile 32x32 (2x2 frags)
// ---------------------------------------------------------------------------
__global__ __launch_bounds__(256) void gemm_tf32_kernel(
    const float* __restrict__ A, const float* __restrict__ Bm,
    const float* __restrict__ bias, int N, int mode, float* __restrict__ out)
{
    __shared__ float sh[9216];          // 36 KB
    float* As = sh;                     // 128 x 40
    float* Bs = sh + 128 * 40;          // 32 x 72
    float* Cs = sh;                     // 128 x 72 (aliases As/Bs after compute)

    const int bm = blockIdx.y * 128;
    const int bn = blockIdx.x * 64;
    const int tid = (int)threadIdx.x;
    const int w = tid >> 5, wm = w >> 1, wn = w & 1;

    const float* Aeff = (mode == 1) ? (const float*)g_attn : A;

    wmma::fragment<wmma::accumulator, 16, 16, 8, float> acc[2][2];
#pragma unroll
    for (int i = 0; i < 2; i++)
#pragma unroll
        for (int j = 0; j < 2; j++) wmma::fill_fragment(acc[i][j], 0.0f);

    for (int k0 = 0; k0 < 1024; k0 += 32) {
        __syncthreads();
#pragma unroll
        for (int p = 0; p < 4; p++) {
            int lin = p * 256 + tid;
            int r = lin >> 3, c = (lin & 7) << 2;
            *(float4*)&As[r * 40 + c] =
                *(const float4*)&Aeff[(size_t)(bm + r) * 1024 + k0 + c];
        }
#pragma unroll
        for (int p = 0; p < 2; p++) {
            int lin = p * 256 + tid;
            int r = lin >> 4, c = (lin & 15) << 2;
            *(float4*)&Bs[r * 72 + c] =
                *(const float4*)&Bm[(size_t)(k0 + r) * N + bn + c];
        }
        __syncthreads();
#pragma unroll
        for (int kk = 0; kk < 32; kk += 8) {
            wmma::fragment<wmma::matrix_a, 16, 16, 8, wmma::precision::tf32, wmma::row_major> af[2];
            wmma::fragment<wmma::matrix_b, 16, 16, 8, wmma::precision::tf32, wmma::row_major> bf[2];
#pragma unroll
            for (int i = 0; i < 2; i++) {
                wmma::load_matrix_sync(af[i], &As[(wm * 32 + i * 16) * 40 + kk], 40);
                frag_to_tf32(af[i]);
            }
#pragma unroll
            for (int j = 0; j < 2; j++) {
                wmma::load_matrix_sync(bf[j], &Bs[kk * 72 + wn * 32 + j * 16], 72);
                frag_to_tf32(bf[j]);
            }
#pragma unroll
            for (int i = 0; i < 2; i++)
#pragma unroll
                for (int j = 0; j < 2; j++)
                    wmma::mma_sync(acc[i][j], af[i], bf[j], acc[i][j]);
        }
    }
    __syncthreads();
#pragma unroll
    for (int i = 0; i < 2; i++)
#pragma unroll
        for (int j = 0; j < 2; j++)
            wmma::store_matrix_sync(&Cs[(wm * 32 + i * 16) * 72 + wn * 32 + j * 16],
                                    acc[i][j], 72, wmma::mem_row_major);
    __syncthreads();

    for (int idx = tid; idx < 128 * 64; idx += 256) {
        int r = idx >> 6, c = idx & 63;
        float val = Cs[r * 72 + c] + bias[bn + c];
        int m = bm + r, gc = bn + c;
        if (mode == 0) {
            // qkv column gc -> head h = gc/192, within = gc%192: [0,64)=Q, [64,128)=K, [128,192)=V
            int b_ = m >> 11, s = m & 2047;
            int h = gc / 192, rr = gc % 192;
            int which = rr >> 6, d = rr & 63;
            float* dst = (which == 0) ? g_q : (which == 1 ? g_k : g_v);
            dst[(((size_t)(b_ * NH + h)) * SEQ + s) * HD + d] = val;
        } else {
            out[(size_t)m * 1024 + gc] = val;
        }
    }
}

// ---------------------------------------------------------------------------
// Causal flash attention, one block per (b, h, q-tile of 64 rows).
// 256 threads = 8 warps (warp grid 4x2 over the 64x64 tile).
// Online softmax; O accumulator in registers (4 threads per row, 16 cols each).
// Output scattered directly into the reference's "no-transpose reshape" layout:
//   g_attn[b][h*128 + s/16][(s%16)*64 + d]
// ---------------------------------------------------------------------------
__global__ __launch_bounds__(256) void attn_kernel(float* __restrict__ attn)
{
    extern __shared__ float sh[];
    float* Qs = sh;             // 64 x 72
    float* Ks = sh + 4608;
    float* Vs = sh + 9216;
    float* Ss = sh + 13824;
    float* Ts = sh + 18432;     // total 23040 floats = 90 KB

    const int bx = (int)blockIdx.x;
    const int qt = bx & 31;
    const int h = (bx >> 5) & 15;
    const int b = bx >> 9;
    const int tid = (int)threadIdx.x;
    const int w = tid >> 5, wm = w >> 1, wn = w & 1;
    const size_t head_base = ((size_t)(b * NH + h)) * SEQ * HD;

    // Load Q tile (pre-scaled by 1/sqrt(D))
    {
        const float scale = 0.125f;
        const float* qp = g_q + head_base + (size_t)qt * 64 * HD;
#pragma unroll
        for (int p = 0; p < 4; p++) {
            int lin = p * 256 + tid;
            int r = lin >> 4, c = (lin & 15) << 2;
            float4 t = *(const float4*)&qp[r * 64 + c];
            t.x *= scale; t.y *= scale; t.z *= scale; t.w *= scale;
            *(float4*)&Qs[r * 72 + c] = t;
        }
    }

    const int row = tid >> 2;          // 0..63
    const int qo = (tid & 3) << 4;     // 0,16,32,48
    float m_i = -INFINITY, l_i = 0.0f;
    float acc_o[16];
#pragma unroll
    for (int i = 0; i < 16; i++) acc_o[i] = 0.0f;

    for (int j = 0; j <= qt; j++) {
        __syncthreads();   // previous iteration's Ks/Vs/Ts fully consumed
        {
            const float* kp = g_k + head_base + (size_t)j * 64 * HD;
            const float* vp = g_v + head_base + (size_t)j * 64 * HD;
#pragma unroll
            for (int p = 0; p < 4; p++) {
                int lin = p * 256 + tid;
                int r = lin >> 4, c = (lin & 15) << 2;
                *(float4*)&Ks[r * 72 + c] = *(const float4*)&kp[r * 64 + c];
                *(float4*)&Vs[r * 72 + c] = *(const float4*)&vp[r * 64 + c];
            }
        }
        __syncthreads();

        // S = (Q*scale) @ K^T  (64x64)
        {
            wmma::fragment<wmma::accumulator, 16, 16, 8, float> sc[2];
            wmma::fill_fragment(sc[0], 0.0f);
            wmma::fill_fragment(sc[1], 0.0f);
#pragma unroll
            for (int kk = 0; kk < 64; kk += 8) {
                wmma::fragment<wmma::matrix_a, 16, 16, 8, wmma::precision::tf32, wmma::row_major> af;
                wmma::load_matrix_sync(af, &Qs[(wm * 16) * 72 + kk], 72);
                frag_to_tf32(af);
#pragma unroll
                for (int n = 0; n < 2; n++) {
                    wmma::fragment<wmma::matrix_b, 16, 16, 8, wmma::precision::tf32, wmma::col_major> bf;
                    wmma::load_matrix_sync(bf, &Ks[(wn * 32 + n * 16) * 72 + kk], 72);
                    frag_to_tf32(bf);
                    wmma::mma_sync(sc[n], af, bf, sc[n]);
                }
            }
#pragma unroll
            for (int n = 0; n < 2; n++)
                wmma::store_matrix_sync(&Ss[(wm * 16) * 72 + wn * 32 + n * 16],
                                        sc[n], 72, wmma::mem_row_major);
        }
        __syncthreads();

        // Online softmax update (4 threads per row)
        {
            const bool diag = (j == qt);
            float sv[16], tmax = -INFINITY;
#pragma unroll
            for (int i = 0; i < 16; i++) {
                int c = qo + i;
                float s = Ss[row * 72 + c];
                if (diag && c > row) s = -INFINITY;   // causal mask (same tile base)
                sv[i] = s;
                tmax = fmaxf(tmax, s);
            }
            tmax = fmaxf(tmax, __shfl_xor_sync(0xffffffffu, tmax, 1));
            tmax = fmaxf(tmax, __shfl_xor_sync(0xffffffffu, tmax, 2));
            float m_new = fmaxf(m_i, tmax);
            float alpha = __expf(m_i - m_new);   // 0 when m_i == -inf
            float lsum = 0.0f;
#pragma unroll
            for (int i = 0; i < 16; i++) {
                float p = __expf(sv[i] - m_new);
                Ss[row * 72 + qo + i] = p;
                lsum += p;
            }
            lsum += __shfl_xor_sync(0xffffffffu, lsum, 1);
            lsum += __shfl_xor_sync(0xffffffffu, lsum, 2);
            l_i = alpha * l_i + lsum;
            m_i = m_new;
#pragma unroll
            for (int i = 0; i < 16; i++) acc_o[i] *= alpha;
        }
        __syncthreads();

        // T = P @ V  (64x64)
        {
            wmma::fragment<wmma::accumulator, 16, 16, 8, float> tv[2];
            wmma::fill_fragment(tv[0], 0.0f);
            wmma::fill_fragment(tv[1], 0.0f);
#pragma unroll
            for (int kk = 0; kk < 64; kk += 8) {
                wmma::fragment<wmma::matrix_a, 16, 16, 8, wmma::precision::tf32, wmma::row_major> af;
                wmma::load_matrix_sync(af, &Ss[(wm * 16) * 72 + kk], 72);
                frag_to_tf32(af);
#pragma unroll
                for (int n = 0; n < 2; n++) {
                    wmma::fragment<wmma::matrix_b, 16, 16, 8, wmma::precision::tf32, wmma::row_major> bf;
                    wmma::load_matrix_sync(bf, &Vs[kk * 72 + wn * 32 + n * 16], 72);
                    frag_to_tf32(bf);
                    wmma::mma_sync(tv[n], af, bf, tv[n]);
                }
            }
#pragma unroll
            for (int n = 0; n < 2; n++)
                wmma::store_matrix_sync(&Ts[(wm * 16) * 72 + wn * 32 + n * 16],
                                        tv[n], 72, wmma::mem_row_major);
        }
        __syncthreads();
#pragma unroll
        for (int i = 0; i < 16; i++) acc_o[i] += Ts[row * 72 + qo + i];
    }

    // Normalize + scatter into the reference's reshape layout
    const float inv_l = 1.0f / l_i;
    const int s_g = qt * 64 + row;
    const size_t dst = ((size_t)b * SEQ + h * 128 + (s_g >> 4)) * EMB
                     + (size_t)(s_g & 15) * 64 + qo;
#pragma unroll
    for (int i = 0; i < 16; i++) attn[dst + i] = acc_o[i] * inv_l;
}

// ---------------------------------------------------------------------------
extern "C" void kernel_launch(void* const* d_in, const int* in_sizes, int n_in,
                              void* d_out, int out_size)
{
    (void)in_sizes; (void)n_in; (void)out_size;
    const float* x    = (const float*)d_in[0];
    // d_in[1] = causal mask (tril) — deterministic, hardcoded in attn_kernel
    const float* Wqkv = (const float*)d_in[2];
    const float* bqkv = (const float*)d_in[3];
    const float* Wo   = (const float*)d_in[4];
    const float* bo   = (const float*)d_in[5];
    float* out = (float*)d_out;

    cudaFuncSetAttribute(attn_kernel,
                         cudaFuncAttributeMaxDynamicSharedMemorySize, 23040 * 4);

    float* attn_ptr = nullptr;
    cudaGetSymbolAddress((void**)&attn_ptr, g_attn);

    // 1) QKV projection: [8192,1024] @ [1024,3072] + bqkv -> scatter Q/K/V
    gemm_tf32_kernel<<<dim3(48, 64), 256>>>(x, Wqkv, bqkv, 3072, 0, nullptr);

    // 2) Causal attention per (b, h, 64-row q-tile)
    attn_kernel<<<BB * NH * (SEQ / 64), 256, 23040 * 4>>>(attn_ptr);

    // 3) Output projection: [8192,1024] @ [1024,1024] + bo -> out
    gemm_tf32_kernel<<<dim3(16, 64), 256>>>(nullptr, Wo, bo, 1024, 1, out);
}

// round 4
// speedup vs baseline: 1.0382x; 1.0382x over previous
#include <cuda_runtime.h>
#include <mma.h>
#include <math.h>

using namespace nvcuda;

#define BB 4
#define SEQ 2048
#define EMB 1024
#define NH 16
#define HD 64

// Scratch (device globals — no allocations allowed)
__device__ float g_q[BB * NH * SEQ * HD];
__device__ float g_k[BB * NH * SEQ * HD];
__device__ float g_v[BB * NH * SEQ * HD];
__device__ float g_attn[BB * SEQ * EMB];

template <class Frag>
__device__ __forceinline__ void frag_to_tf32(Frag& f) {
#pragma unroll
    for (int t = 0; t < f.num_elements; t++) f.x[t] = wmma::__float_to_tf32(f.x[t]);
}

__device__ __forceinline__ void cp16(float* smem, const float* gmem) {
    unsigned a = (unsigned)__cvta_generic_to_shared(smem);
    asm volatile("cp.async.ca.shared.global [%0], [%1], 16;\n" :: "r"(a), "l"(gmem));
}

// ---------------------------------------------------------------------------
// TF32 GEMM, double-buffered cp.async: C[8192 x N] = A[8192x1024] @ B[1024xN] + bias
// BM=128, BN=128, BK=32, 256 threads, warp grid 2x4, warp tile 64x32 (4x2 frags)
//  mode 0: A = x, epilogue scatters into g_q/g_k/g_v ([B,H,S,D] layout)
//  mode 1: A = g_attn, epilogue writes out
// smem: As[2][128][40], Bs[2][32][136]  (= 75776 B); C reuses (128x136 = 69632 B)
// ---------------------------------------------------------------------------
__global__ __launch_bounds__(256) void gemm_tf32_kernel(
    const float* __restrict__ A, const float* __restrict__ Bm,
    const float* __restrict__ bias, int N, int mode, float* __restrict__ out)
{
    extern __shared__ float sh[];
    float* As0 = sh;                 // 5120
    float* As1 = sh + 5120;
    float* Bs0 = sh + 10240;         // 4352
    float* Bs1 = sh + 14592;
    float* Asb[2] = {As0, As1};
    float* Bsb[2] = {Bs0, Bs1};
    float* Cs = sh;                  // 128 x 136 after compute

    const int bm = blockIdx.y * 128;
    const int bn = blockIdx.x * 128;
    const int tid = (int)threadIdx.x;
    const int w = tid >> 5, wm = w >> 2, wn = w & 3;

    const float* Aeff = (mode == 1) ? (const float*)g_attn : A;

    auto load_stage = [&](int st, int k0) {
#pragma unroll
        for (int p = 0; p < 4; p++) {                  // A: 128x32 = 1024 float4
            int lin = p * 256 + tid;
            int r = lin >> 3, c = (lin & 7) << 2;
            cp16(&Asb[st][r * 40 + c], &Aeff[(size_t)(bm + r) * 1024 + k0 + c]);
        }
#pragma unroll
        for (int p = 0; p < 4; p++) {                  // B: 32x128 = 1024 float4
            int lin = p * 256 + tid;
            int r = lin >> 5, c = (lin & 31) << 2;
            cp16(&Bsb[st][r * 136 + c], &Bm[(size_t)(k0 + r) * N + bn + c]);
        }
    };

    wmma::fragment<wmma::accumulator, 16, 16, 8, float> acc[4][2];
#pragma unroll
    for (int i = 0; i < 4; i++)
#pragma unroll
        for (int j = 0; j < 2; j++) wmma::fill_fragment(acc[i][j], 0.0f);

    load_stage(0, 0);
    asm volatile("cp.async.commit_group;\n");

    for (int kt = 0; kt < 32; kt++) {
        const int cur = kt & 1;
        if (kt < 31) {
            load_stage(cur ^ 1, (kt + 1) * 32);
            asm volatile("cp.async.commit_group;\n");
            asm volatile("cp.async.wait_group 1;\n");
        } else {
            asm volatile("cp.async.wait_group 0;\n");
        }
        __syncthreads();

        const float* Asc = Asb[cur];
        const float* Bsc = Bsb[cur];
#pragma unroll
        for (int kk = 0; kk < 32; kk += 8) {
            wmma::fragment<wmma::matrix_a, 16, 16, 8, wmma::precision::tf32, wmma::row_major> af[4];
            wmma::fragment<wmma::matrix_b, 16, 16, 8, wmma::precision::tf32, wmma::row_major> bf[2];
#pragma unroll
            for (int i = 0; i < 4; i++) {
                wmma::load_matrix_sync(af[i], &Asc[(wm * 64 + i * 16) * 40 + kk], 40);
                frag_to_tf32(af[i]);
            }
#pragma unroll
            for (int j = 0; j < 2; j++) {
                wmma::load_matrix_sync(bf[j], &Bsc[kk * 136 + wn * 32 + j * 16], 136);
                frag_to_tf32(bf[j]);
            }
#pragma unroll
            for (int i = 0; i < 4; i++)
#pragma unroll
                for (int j = 0; j < 2; j++)
                    wmma::mma_sync(acc[i][j], af[i], bf[j], acc[i][j]);
        }
        __syncthreads();
    }

#pragma unroll
    for (int i = 0; i < 4; i++)
#pragma unroll
        for (int j = 0; j < 2; j++)
            wmma::store_matrix_sync(&Cs[(wm * 64 + i * 16) * 136 + wn * 32 + j * 16],
                                    acc[i][j], 136, wmma::mem_row_major);
    __syncthreads();

    for (int idx = tid; idx < 128 * 128; idx += 256) {
        int r = idx >> 7, c = idx & 127;
        float val = Cs[r * 136 + c] + bias[bn + c];
        int m = bm + r, gc = bn + c;
        if (mode == 0) {
            int b_ = m >> 11, s = m & 2047;
            int h = gc / 192, rr = gc % 192;
            int which = rr >> 6, d = rr & 63;
            float* dst = (which == 0) ? g_q : (which == 1 ? g_k : g_v);
            dst[(((size_t)(b_ * NH + h)) * SEQ + s) * HD + d] = val;
        } else {
            out[(size_t)m * 1024 + gc] = val;
        }
    }
}

// ---------------------------------------------------------------------------
// Causal flash attention (FA-2 style). One block per (b, h, 128-row q-tile).
// 256 threads = 8 warps; warp wid owns q-rows [wid*16, wid*16+16) end-to-end.
// Per KV tile (64 rows): only 2 block syncs (around K/V load); softmax / P / O
// traffic is warp-local (strip smem + __syncwarp). O accumulators: 2 lanes per
// row, 32 cols each (lane -> row lane>>1, col half (lane&1)*32).
// smem: Qs 128x72 | Ks 64x72 | Vs 64x72 | Ps 128x72 (S, then P, then O-tile)
// ---------------------------------------------------------------------------
__global__ __launch_bounds__(256) void attn_kernel(float* __restrict__ attn)
{
    extern __shared__ float sh[];
    float* Qs = sh;              // 9216
    float* Ks = sh + 9216;       // 4608
    float* Vs = sh + 13824;      // 4608
    float* Ps = sh + 18432;      // 9216  (total 27648 floats = 110592 B)

    const int bx = (int)blockIdx.x;
    const int qt = bx & 15;
    const int h = (bx >> 4) & 15;
    const int b = bx >> 8;
    const int tid = (int)threadIdx.x;
    const int wid = tid >> 5, lane = tid & 31;
    const size_t head_base = ((size_t)(b * NH + h)) * SEQ * HD;

    // Load Q tile (128x64), pre-scaled by 1/sqrt(D)
    {
        const float* qp = g_q + head_base + (size_t)qt * 128 * HD;
#pragma unroll
        for (int p = 0; p < 8; p++) {
            int lin = p * 256 + tid;
            int r = lin >> 4, c = (lin & 15) << 2;
            float4 t = *(const float4*)&qp[r * 64 + c];
            t.x *= 0.125f; t.y *= 0.125f; t.z *= 0.125f; t.w *= 0.125f;
            *(float4*)&Qs[r * 72 + c] = t;
        }
    }

    // per-lane row ownership
    const int rr = lane >> 1;              // local row in warp strip (0..15)
    const int ch = (lane & 1) << 5;        // col half: 0 or 32
    const int row_g = qt * 128 + wid * 16 + rr;   // global q row
    float* strip_row = &Ps[(wid * 16 + rr) * 72 + ch];

    float m_i = -INFINITY, l_i = 0.0f;
    float o[32];
#pragma unroll
    for (int i = 0; i < 32; i++) o[i] = 0.0f;

    const int njt = 2 * qt + 2;
    for (int j = 0; j < njt; j++) {
        __syncthreads();   // everyone done with previous Ks/Vs
        {
            const float* kp = g_k + head_base + (size_t)j * 64 * HD;
            const float* vp = g_v + head_base + (size_t)j * 64 * HD;
#pragma unroll
            for (int p = 0; p < 4; p++) {
                int lin = p * 256 + tid;
                int r = lin >> 4, c = (lin & 15) << 2;
                *(float4*)&Ks[r * 72 + c] = *(const float4*)&kp[r * 64 + c];
                *(float4*)&Vs[r * 72 + c] = *(const float4*)&vp[r * 64 + c];
            }
        }
        __syncthreads();

        // ---- S = (Q*scale) @ K^T for this warp's 16x64 strip ----
        {
            wmma::fragment<wmma::accumulator, 16, 16, 8, float> sf[4];
#pragma unroll
            for (int n = 0; n < 4; n++) wmma::fill_fragment(sf[n], 0.0f);
#pragma unroll
            for (int kk = 0; kk < 64; kk += 8) {
                wmma::fragment<wmma::matrix_a, 16, 16, 8, wmma::precision::tf32, wmma::row_major> af;
                wmma::load_matrix_sync(af, &Qs[(wid * 16) * 72 + kk], 72);
                frag_to_tf32(af);
#pragma unroll
                for (int n = 0; n < 4; n++) {
                    wmma::fragment<wmma::matrix_b, 16, 16, 8, wmma::precision::tf32, wmma::col_major> bf;
                    wmma::load_matrix_sync(bf, &Ks[(n * 16) * 72 + kk], 72);
                    frag_to_tf32(bf);
                    wmma::mma_sync(sf[n], af, bf, sf[n]);
                }
            }
#pragma unroll
            for (int n = 0; n < 4; n++)
                wmma::store_matrix_sync(&Ps[(wid * 16) * 72 + n * 16], sf[n], 72,
                                        wmma::mem_row_major);
        }
        __syncwarp();

        // ---- online softmax on this lane's row half (warp-local) ----
        float alpha;
        {
            const int colbase = j * 64 + ch;
            float sv[32];
            float rmax = -INFINITY;
#pragma unroll
            for (int i4 = 0; i4 < 8; i4++) {
                float4 t = *(float4*)&strip_row[i4 * 4];
                sv[i4*4+0] = (colbase + i4*4 + 0 <= row_g) ? t.x : -INFINITY;
                sv[i4*4+1] = (colbase + i4*4 + 1 <= row_g) ? t.y : -INFINITY;
                sv[i4*4+2] = (colbase + i4*4 + 2 <= row_g) ? t.z : -INFINITY;
                sv[i4*4+3] = (colbase + i4*4 + 3 <= row_g) ? t.w : -INFINITY;
            }
#pragma unroll
            for (int i = 0; i < 32; i++) rmax = fmaxf(rmax, sv[i]);
            rmax = fmaxf(rmax, __shfl_xor_sync(0xffffffffu, rmax, 1));
            float m_new = fmaxf(m_i, rmax);
            alpha = __expf(m_i - m_new);      // 0 when m_i == -inf
            float lsum = 0.0f;
#pragma unroll
            for (int i4 = 0; i4 < 8; i4++) {
                float4 t;
                t.x = __expf(sv[i4*4+0] - m_new);
                t.y = __expf(sv[i4*4+1] - m_new);
                t.z = __expf(sv[i4*4+2] - m_new);
                t.w = __expf(sv[i4*4+3] - m_new);
                lsum += t.x + t.y + t.z + t.w;
                *(float4*)&strip_row[i4 * 4] = t;
            }
            lsum += __shfl_xor_sync(0xffffffffu, lsum, 1);
            l_i = alpha * l_i + lsum;
            m_i = m_new;
        }
        __syncwarp();

        // ---- T = P @ V for this warp's strip; result overwrites strip ----
        {
            wmma::fragment<wmma::accumulator, 16, 16, 8, float> tf[4];
#pragma unroll
            for (int n = 0; n < 4; n++) wmma::fill_fragment(tf[n], 0.0f);
#pragma unroll
            for (int kk = 0; kk < 64; kk += 8) {
                wmma::fragment<wmma::matrix_a, 16, 16, 8, wmma::precision::tf32, wmma::row_major> af;
                wmma::load_matrix_sync(af, &Ps[(wid * 16) * 72 + kk], 72);
                frag_to_tf32(af);
#pragma unroll
                for (int n = 0; n < 4; n++) {
                    wmma::fragment<wmma::matrix_b, 16, 16, 8, wmma::precision::tf32, wmma::row_major> bf;
                    wmma::load_matrix_sync(bf, &Vs[kk * 72 + n * 16], 72);
                    frag_to_tf32(bf);
                    wmma::mma_sync(tf[n], af, bf, tf[n]);
                }
            }
#pragma unroll
            for (int n = 0; n < 4; n++)
                wmma::store_matrix_sync(&Ps[(wid * 16) * 72 + n * 16], tf[n], 72,
                                        wmma::mem_row_major);
        }
        __syncwarp();

        // ---- O update: o = o*alpha + T (lane-owned row half) ----
#pragma unroll
        for (int i4 = 0; i4 < 8; i4++) {
            float4 t = *(float4*)&strip_row[i4 * 4];
            o[i4*4+0] = o[i4*4+0] * alpha + t.x;
            o[i4*4+1] = o[i4*4+1] * alpha + t.y;
            o[i4*4+2] = o[i4*4+2] * alpha + t.z;
            o[i4*4+3] = o[i4*4+3] * alpha + t.w;
        }
    }

    // Normalize + scatter into the reference's "no-transpose reshape" layout:
    // attn[b][h*128 + s/16][(s%16)*64 + d]
    const float inv_l = 1.0f / l_i;
    const int s_g = row_g;
    float* dst = attn + ((size_t)b * SEQ + h * 128 + (s_g >> 4)) * EMB
               + (size_t)(s_g & 15) * 64 + ch;
#pragma unroll
    for (int i4 = 0; i4 < 8; i4++) {
        float4 t;
        t.x = o[i4*4+0] * inv_l;
        t.y = o[i4*4+1] * inv_l;
        t.z = o[i4*4+2] * inv_l;
        t.w = o[i4*4+3] * inv_l;
        *(float4*)&dst[i4 * 4] = t;
    }
}

// ---------------------------------------------------------------------------
extern "C" void kernel_launch(void* const* d_in, const int* in_sizes, int n_in,
                              void* d_out, int out_size)
{
    (void)in_sizes; (void)n_in; (void)out_size;
    const float* x    = (const float*)d_in[0];
    // d_in[1] = causal mask (tril) — deterministic, hardcoded in attn_kernel
    const float* Wqkv = (const float*)d_in[2];
    const float* bqkv = (const float*)d_in[3];
    const float* Wo   = (const float*)d_in[4];
    const float* bo   = (const float*)d_in[5];
    float* out = (float*)d_out;

    static int init = 0;
    if (!init) {
        cudaFuncSetAttribute(gemm_tf32_kernel,
                             cudaFuncAttributeMaxDynamicSharedMemorySize, 75776);
        cudaFuncSetAttribute(attn_kernel,
                             cudaFuncAttributeMaxDynamicSharedMemorySize, 110592);
        init = 1;
    }

    float* attn_ptr = nullptr;
    cudaGetSymbolAddress((void**)&attn_ptr, g_attn);

    // 1) QKV projection: [8192,1024] @ [1024,3072] + bqkv -> scatter Q/K/V
    gemm_tf32_kernel<<<dim3(24, 64), 256, 75776>>>(x, Wqkv, bqkv, 3072, 0, nullptr);

    // 2) Causal attention per (b, h, 128-row q-tile)
    attn_kernel<<<BB * NH * (SEQ / 128), 256, 110592>>>(attn_ptr);

    // 3) Output projection: [8192,1024] @ [1024,1024] + bo -> out
    gemm_tf32_kernel<<<dim3(8, 64), 256, 75776>>>(nullptr, Wo, bo, 1024, 1, out);
}

// round 9
// speedup vs baseline: 1.1315x; 1.0899x over previous
#include <cuda_runtime.h>
#include <mma.h>
#include <math.h>

using namespace nvcuda;

#define BB 4
#define SEQ 2048
#define EMB 1024
#define NH 16
#define HD 64

// Scratch (device globals — no allocations allowed)
__device__ float g_q[BB * NH * SEQ * HD];
__device__ float g_k[BB * NH * SEQ * HD];
__device__ float g_v[BB * NH * SEQ * HD];
__device__ float g_attn[BB * SEQ * EMB];
__device__ float g_xr[BB * SEQ * EMB];        // tf32-rounded x
__device__ float g_wqkv[EMB * 3 * EMB];       // tf32-rounded Wqkv
__device__ float g_wo[EMB * EMB];             // tf32-rounded Wo

__device__ __forceinline__ float rtf32(float x) {
    float r; asm("cvt.rna.tf32.f32 %0, %1;" : "=f"(r) : "f"(x)); return r;
}
__device__ __forceinline__ void cp16(float* smem, const float* gmem) {
    unsigned a = (unsigned)__cvta_generic_to_shared(smem);
    asm volatile("cp.async.ca.shared.global [%0], [%1], 16;\n" :: "r"(a), "l"(gmem));
}

// ---------------------------------------------------------------------------
// Round-to-nearest tf32 pre-pass (element-wise, float4)
// ---------------------------------------------------------------------------
__global__ void round_tf32_kernel(const float* __restrict__ src,
                                  float* __restrict__ dst, int n4) {
    int i = blockIdx.x * blockDim.x + threadIdx.x;
    if (i < n4) {
        float4 t = ((const float4*)src)[i];
        t.x = rtf32(t.x); t.y = rtf32(t.y); t.z = rtf32(t.z); t.w = rtf32(t.w);
        ((float4*)dst)[i] = t;
    }
}

// ---------------------------------------------------------------------------
// TF32 GEMM, double-buffered cp.async: C[8192 x N] = A[8192x1024] @ B[1024xN] + bias
// BM=128, BN=128, BK=32, 256 threads, warp grid 2x4, warp tile 64x32 (4x2 frags)
// Operands are PRE-ROUNDED to tf32 -> no per-fragment conversions needed.
//  mode 0: A = g_xr, B = g_wqkv; epilogue rounds + scatters into g_q/g_k/g_v
//  mode 1: A = g_attn (rounded), B = g_wo; epilogue writes out (fp32)
// ---------------------------------------------------------------------------
__global__ __launch_bounds__(256, 2) void gemm_tf32_kernel(
    const float* __restrict__ A, const float* __restrict__ Bm,
    const float* __restrict__ bias, int N, int mode, float* __restrict__ out)
{
    extern __shared__ float sh[];
    float* Asb[2] = { sh,         sh + 5120 };   // 128 x 40 each
    float* Bsb[2] = { sh + 10240, sh + 14592 };  // 32 x 136 each
    float* Cs = sh;                              // 128 x 136 after compute

    const int bm = blockIdx.y * 128;
    const int bn = blockIdx.x * 128;
    const int tid = (int)threadIdx.x;
    const int w = tid >> 5, wm = w >> 2, wn = w & 3;

    const float* Aeff = (mode == 1) ? (const float*)g_attn : A;

    auto load_stage = [&](int st, int k0) {
#pragma unroll
        for (int p = 0; p < 4; p++) {                  // A: 128x32 = 1024 float4
            int lin = p * 256 + tid;
            int r = lin >> 3, c = (lin & 7) << 2;
            cp16(&Asb[st][r * 40 + c], &Aeff[(size_t)(bm + r) * 1024 + k0 + c]);
        }
#pragma unroll
        for (int p = 0; p < 4; p++) {                  // B: 32x128 = 1024 float4
            int lin = p * 256 + tid;
            int r = lin >> 5, c = (lin & 31) << 2;
            cp16(&Bsb[st][r * 136 + c], &Bm[(size_t)(k0 + r) * N + bn + c]);
        }
    };

    wmma::fragment<wmma::accumulator, 16, 16, 8, float> acc[4][2];
#pragma unroll
    for (int i = 0; i < 4; i++)
#pragma unroll
        for (int j = 0; j < 2; j++) wmma::fill_fragment(acc[i][j], 0.0f);

    load_stage(0, 0);
    asm volatile("cp.async.commit_group;\n");

    for (int kt = 0; kt < 32; kt++) {
        const int cur = kt & 1;
        if (kt < 31) {
            load_stage(cur ^ 1, (kt + 1) * 32);
            asm volatile("cp.async.commit_group;\n");
            asm volatile("cp.async.wait_group 1;\n");
        } else {
            asm volatile("cp.async.wait_group 0;\n");
        }
        __syncthreads();

        const float* Asc = Asb[cur];
        const float* Bsc = Bsb[cur];
#pragma unroll
        for (int kk = 0; kk < 32; kk += 8) {
            wmma::fragment<wmma::matrix_a, 16, 16, 8, wmma::precision::tf32, wmma::row_major> af[4];
            wmma::fragment<wmma::matrix_b, 16, 16, 8, wmma::precision::tf32, wmma::row_major> bf[2];
#pragma unroll
            for (int i = 0; i < 4; i++)
                wmma::load_matrix_sync(af[i], &Asc[(wm * 64 + i * 16) * 40 + kk], 40);
#pragma unroll
            for (int j = 0; j < 2; j++)
                wmma::load_matrix_sync(bf[j], &Bsc[kk * 136 + wn * 32 + j * 16], 136);
#pragma unroll
            for (int i = 0; i < 4; i++)
#pragma unroll
                for (int j = 0; j < 2; j++)
                    wmma::mma_sync(acc[i][j], af[i], bf[j], acc[i][j]);
        }
        __syncthreads();
    }

#pragma unroll
    for (int i = 0; i < 4; i++)
#pragma unroll
        for (int j = 0; j < 2; j++)
            wmma::store_matrix_sync(&Cs[(wm * 64 + i * 16) * 136 + wn * 32 + j * 16],
                                    acc[i][j], 136, wmma::mem_row_major);
    __syncthreads();

    for (int idx = tid; idx < 128 * 128; idx += 256) {
        int r = idx >> 7, c = idx & 127;
        float val = Cs[r * 136 + c] + bias[bn + c];
        int m = bm + r, gc = bn + c;
        if (mode == 0) {
            int b_ = m >> 11, s = m & 2047;
            int h = gc / 192, rr = gc % 192;
            int which = rr >> 6, d = rr & 63;
            float* dst = (which == 0) ? g_q : (which == 1 ? g_k : g_v);
            // round: downstream attention consumes these as tf32 HMMA operands
            dst[(((size_t)(b_ * NH + h)) * SEQ + s) * HD + d] = rtf32(val);
        } else {
            out[(size_t)m * 1024 + gc] = val;
        }
    }
}

// ---------------------------------------------------------------------------
// Causal flash attention (FA-2 style). One block per (b, h, 128-row q-tile).
// 256 threads = 8 warps; warp wid owns q-rows [wid*16, wid*16+16) end-to-end.
// All wmma operands (Q,K,V from rounded g_q/g_k/g_v; P rounded post-exp) are
// already tf32-valued -> no fragment conversions.
// ---------------------------------------------------------------------------
__global__ __launch_bounds__(256) void attn_kernel(float* __restrict__ attn)
{
    extern __shared__ float sh[];
    float* Qs = sh;              // 9216
    float* Ks = sh + 9216;       // 4608
    float* Vs = sh + 13824;      // 4608
    float* Ps = sh + 18432;      // 9216

    const int bx = (int)blockIdx.x;
    const int qt = bx & 15;
    const int h = (bx >> 4) & 15;
    const int b = bx >> 8;
    const int tid = (int)threadIdx.x;
    const int wid = tid >> 5, lane = tid & 31;
    const size_t head_base = ((size_t)(b * NH + h)) * SEQ * HD;

    // Load Q tile (128x64), pre-scaled by 1/sqrt(D)=0.125 (exact power of 2:
    // preserves tf32-ness of the rounded g_q values)
    {
        const float* qp = g_q + head_base + (size_t)qt * 128 * HD;
#pragma unroll
        for (int p = 0; p < 8; p++) {
            int lin = p * 256 + tid;
            int r = lin >> 4, c = (lin & 15) << 2;
            float4 t = *(const float4*)&qp[r * 64 + c];
            t.x *= 0.125f; t.y *= 0.125f; t.z *= 0.125f; t.w *= 0.125f;
            *(float4*)&Qs[r * 72 + c] = t;
        }
    }

    const int rr = lane >> 1;
    const int ch = (lane & 1) << 5;
    const int row_g = qt * 128 + wid * 16 + rr;
    float* strip_row = &Ps[(wid * 16 + rr) * 72 + ch];

    float m_i = -INFINITY, l_i = 0.0f;
    float o[32];
#pragma unroll
    for (int i = 0; i < 32; i++) o[i] = 0.0f;

    const int njt = 2 * qt + 2;
    for (int j = 0; j < njt; j++) {
        __syncthreads();
        {
            const float* kp = g_k + head_base + (size_t)j * 64 * HD;
            const float* vp = g_v + head_base + (size_t)j * 64 * HD;
#pragma unroll
            for (int p = 0; p < 4; p++) {
                int lin = p * 256 + tid;
                int r = lin >> 4, c = (lin & 15) << 2;
                *(float4*)&Ks[r * 72 + c] = *(const float4*)&kp[r * 64 + c];
                *(float4*)&Vs[r * 72 + c] = *(const float4*)&vp[r * 64 + c];
            }
        }
        __syncthreads();

        // ---- S = (Q*scale) @ K^T for this warp's 16x64 strip ----
        {
            wmma::fragment<wmma::accumulator, 16, 16, 8, float> sf[4];
#pragma unroll
            for (int n = 0; n < 4; n++) wmma::fill_fragment(sf[n], 0.0f);
#pragma unroll
            for (int kk = 0; kk < 64; kk += 8) {
                wmma::fragment<wmma::matrix_a, 16, 16, 8, wmma::precision::tf32, wmma::row_major> af;
                wmma::load_matrix_sync(af, &Qs[(wid * 16) * 72 + kk], 72);
#pragma unroll
                for (int n = 0; n < 4; n++) {
                    wmma::fragment<wmma::matrix_b, 16, 16, 8, wmma::precision::tf32, wmma::col_major> bf;
                    wmma::load_matrix_sync(bf, &Ks[(n * 16) * 72 + kk], 72);
                    wmma::mma_sync(sf[n], af, bf, sf[n]);
                }
            }
#pragma unroll
            for (int n = 0; n < 4; n++)
                wmma::store_matrix_sync(&Ps[(wid * 16) * 72 + n * 16], sf[n], 72,
                                        wmma::mem_row_major);
        }
        __syncwarp();

        // ---- online softmax on this lane's row half (warp-local) ----
        float alpha;
        {
            const int colbase = j * 64 + ch;
            float sv[32];
            float rmax = -INFINITY;
#pragma unroll
            for (int i4 = 0; i4 < 8; i4++) {
                float4 t = *(float4*)&strip_row[i4 * 4];
                sv[i4*4+0] = (colbase + i4*4 + 0 <= row_g) ? t.x : -INFINITY;
                sv[i4*4+1] = (colbase + i4*4 + 1 <= row_g) ? t.y : -INFINITY;
                sv[i4*4+2] = (colbase + i4*4 + 2 <= row_g) ? t.z : -INFINITY;
                sv[i4*4+3] = (colbase + i4*4 + 3 <= row_g) ? t.w : -INFINITY;
            }
#pragma unroll
            for (int i = 0; i < 32; i++) rmax = fmaxf(rmax, sv[i]);
            rmax = fmaxf(rmax, __shfl_xor_sync(0xffffffffu, rmax, 1));
            float m_new = fmaxf(m_i, rmax);
            alpha = __expf(m_i - m_new);      // 0 when m_i == -inf
            float lsum = 0.0f;
#pragma unroll
            for (int i4 = 0; i4 < 8; i4++) {
                float4 t;
                t.x = __expf(sv[i4*4+0] - m_new);
                t.y = __expf(sv[i4*4+1] - m_new);
                t.z = __expf(sv[i4*4+2] - m_new);
                t.w = __expf(sv[i4*4+3] - m_new);
                lsum += t.x + t.y + t.z + t.w;   // fp32 row-sum (exact path)
                // round P for the tf32 PV mma (replaces per-fragment conversion)
                t.x = rtf32(t.x); t.y = rtf32(t.y);
                t.z = rtf32(t.z); t.w = rtf32(t.w);
                *(float4*)&strip_row[i4 * 4] = t;
            }
            lsum += __shfl_xor_sync(0xffffffffu, lsum, 1);
            l_i = alpha * l_i + lsum;
            m_i = m_new;
        }
        __syncwarp();

        // ---- T = P @ V for this warp's strip; result overwrites strip ----
        {
            wmma::fragment<wmma::accumulator, 16, 16, 8, float> tf[4];
#pragma unroll
            for (int n = 0; n < 4; n++) wmma::fill_fragment(tf[n], 0.0f);
#pragma unroll
            for (int kk = 0; kk < 64; kk += 8) {
                wmma::fragment<wmma::matrix_a, 16, 16, 8, wmma::precision::tf32, wmma::row_major> af;
                wmma::load_matrix_sync(af, &Ps[(wid * 16) * 72 + kk], 72);
#pragma unroll
                for (int n = 0; n < 4; n++) {
                    wmma::fragment<wmma::matrix_b, 16, 16, 8, wmma::precision::tf32, wmma::row_major> bf;
                    wmma::load_matrix_sync(bf, &Vs[kk * 72 + n * 16], 72);
                    wmma::mma_sync(tf[n], af, bf, tf[n]);
                }
            }
#pragma unroll
            for (int n = 0; n < 4; n++)
                wmma::store_matrix_sync(&Ps[(wid * 16) * 72 + n * 16], tf[n], 72,
                                        wmma::mem_row_major);
        }
        __syncwarp();

#pragma unroll
        for (int i4 = 0; i4 < 8; i4++) {
            float4 t = *(float4*)&strip_row[i4 * 4];
            o[i4*4+0] = o[i4*4+0] * alpha + t.x;
            o[i4*4+1] = o[i4*4+1] * alpha + t.y;
            o[i4*4+2] = o[i4*4+2] * alpha + t.z;
            o[i4*4+3] = o[i4*4+3] * alpha + t.w;
        }
    }

    // Normalize, round (GEMM2 consumes as tf32), scatter into reshape layout:
    // attn[b][h*128 + s/16][(s%16)*64 + d]
    const float inv_l = 1.0f / l_i;
    const int s_g = row_g;
    float* dst = attn + ((size_t)b * SEQ + h * 128 + (s_g >> 4)) * EMB
               + (size_t)(s_g & 15) * 64 + ch;
#pragma unroll
    for (int i4 = 0; i4 < 8; i4++) {
        float4 t;
        t.x = rtf32(o[i4*4+0] * inv_l);
        t.y = rtf32(o[i4*4+1] * inv_l);
        t.z = rtf32(o[i4*4+2] * inv_l);
        t.w = rtf32(o[i4*4+3] * inv_l);
        *(float4*)&dst[i4 * 4] = t;
    }
}

// ---------------------------------------------------------------------------
extern "C" void kernel_launch(void* const* d_in, const int* in_sizes, int n_in,
                              void* d_out, int out_size)
{
    (void)in_sizes; (void)n_in; (void)out_size;
    const float* x    = (const float*)d_in[0];
    // d_in[1] = causal mask (tril) — deterministic, hardcoded in attn_kernel
    const float* Wqkv = (const float*)d_in[2];
    const float* bqkv = (const float*)d_in[3];
    const float* Wo   = (const float*)d_in[4];
    const float* bo   = (const float*)d_in[5];
    float* out = (float*)d_out;

    static int init = 0;
    if (!init) {
        cudaFuncSetAttribute(gemm_tf32_kernel,
                             cudaFuncAttributeMaxDynamicSharedMemorySize, 75776);
        cudaFuncSetAttribute(attn_kernel,
                             cudaFuncAttributeMaxDynamicSharedMemorySize, 110592);
        init = 1;
    }

    float *attn_ptr, *xr_ptr, *wqkv_ptr, *wo_ptr;
    cudaGetSymbolAddress((void**)&attn_ptr, g_attn);
    cudaGetSymbolAddress((void**)&xr_ptr, g_xr);
    cudaGetSymbolAddress((void**)&wqkv_ptr, g_wqkv);
    cudaGetSymbolAddress((void**)&wo_ptr, g_wo);

    // 0) round inputs to nearest-tf32 once (removes all per-fragment converts)
    round_tf32_kernel<<<(2097152 + 255) / 256, 256>>>(x, xr_ptr, 2097152);
    round_tf32_kernel<<<(786432 + 255) / 256, 256>>>(Wqkv, wqkv_ptr, 786432);
    round_tf32_kernel<<<(262144 + 255) / 256, 256>>>(Wo, wo_ptr, 262144);

    // 1) QKV projection: [8192,1024] @ [1024,3072] + bqkv -> Q/K/V (rounded)
    gemm_tf32_kernel<<<dim3(24, 64), 256, 75776>>>(xr_ptr, wqkv_ptr, bqkv, 3072, 0, nullptr);

    // 2) Causal attention per (b, h, 128-row q-tile)
    attn_kernel<<<BB * NH * (SEQ / 128), 256, 110592>>>(attn_ptr);

    // 3) Output projection: [8192,1024] @ [1024,1024] + bo -> out
    gemm_tf32_kernel<<<dim3(8, 64), 256, 75776>>>(nullptr, wo_ptr, bo, 1024, 1, out);
}

// round 10
// speedup vs baseline: 1.1518x; 1.0179x over previous
#include <cuda_runtime.h>
#include <mma.h>
#include <math.h>

using namespace nvcuda;

#define BB 4
#define SEQ 2048
#define EMB 1024
#define NH 16
#define HD 64

// Scratch (device globals — no allocations allowed)
__device__ float g_q[BB * NH * SEQ * HD];
__device__ float g_k[BB * NH * SEQ * HD];
__device__ float g_v[BB * NH * SEQ * HD];
__device__ float g_attn[BB * SEQ * EMB];
__device__ float g_xr[BB * SEQ * EMB];        // tf32-rounded x
__device__ float g_wqkv[EMB * 3 * EMB];       // tf32-rounded Wqkv
__device__ float g_wo[EMB * EMB];             // tf32-rounded Wo

__device__ __forceinline__ float rtf32(float x) {
    float r; asm("cvt.rna.tf32.f32 %0, %1;" : "=f"(r) : "f"(x)); return r;
}
__device__ __forceinline__ void cp16(float* smem, const float* gmem) {
    unsigned a = (unsigned)__cvta_generic_to_shared(smem);
    asm volatile("cp.async.ca.shared.global [%0], [%1], 16;\n" :: "r"(a), "l"(gmem));
}

// ---------------------------------------------------------------------------
// Round-to-nearest tf32 pre-pass (element-wise, float4)
// ---------------------------------------------------------------------------
__global__ void round_tf32_kernel(const float* __restrict__ src,
                                  float* __restrict__ dst, int n4) {
    int i = blockIdx.x * blockDim.x + threadIdx.x;
    if (i < n4) {
        float4 t = ((const float4*)src)[i];
        t.x = rtf32(t.x); t.y = rtf32(t.y); t.z = rtf32(t.z); t.w = rtf32(t.w);
        ((float4*)dst)[i] = t;
    }
}

// ---------------------------------------------------------------------------
// TF32 GEMM, double-buffered cp.async: C[8192 x N] = A[8192x1024] @ B[1024xN] + bias
// BM=128, BN=128, BK=32, 256 threads, warp grid 2x4, warp tile 64x32 (4x2 frags)
// smem skew: A stride 36 (2-way max conflicts), B/C stride 132.
//  mode 0: A = g_xr, B = g_wqkv; epilogue rounds + scatters into g_q/g_k/g_v
//  mode 1: A = g_attn (rounded), B = g_wo; epilogue writes out (fp32)
// ---------------------------------------------------------------------------
__global__ __launch_bounds__(256, 2) void gemm_tf32_kernel(
    const float* __restrict__ A, const float* __restrict__ Bm,
    const float* __restrict__ bias, int N, int mode, float* __restrict__ out)
{
    extern __shared__ float sh[];
    float* Asb[2] = { sh,        sh + 4608 };   // 128 x 36 each
    float* Bsb[2] = { sh + 9216, sh + 13440 };  // 32 x 132 each
    float* Cs = sh;                             // 128 x 132 after compute

    const int bm = blockIdx.y * 128;
    const int bn = blockIdx.x * 128;
    const int tid = (int)threadIdx.x;
    const int w = tid >> 5, wm = w >> 2, wn = w & 3;

    const float* Aeff = (mode == 1) ? (const float*)g_attn : A;

    auto load_stage = [&](int st, int k0) {
#pragma unroll
        for (int p = 0; p < 4; p++) {                  // A: 128x32 = 1024 float4
            int lin = p * 256 + tid;
            int r = lin >> 3, c = (lin & 7) << 2;
            cp16(&Asb[st][r * 36 + c], &Aeff[(size_t)(bm + r) * 1024 + k0 + c]);
        }
#pragma unroll
        for (int p = 0; p < 4; p++) {                  // B: 32x128 = 1024 float4
            int lin = p * 256 + tid;
            int r = lin >> 5, c = (lin & 31) << 2;
            cp16(&Bsb[st][r * 132 + c], &Bm[(size_t)(k0 + r) * N + bn + c]);
        }
    };

    wmma::fragment<wmma::accumulator, 16, 16, 8, float> acc[4][2];
#pragma unroll
    for (int i = 0; i < 4; i++)
#pragma unroll
        for (int j = 0; j < 2; j++) wmma::fill_fragment(acc[i][j], 0.0f);

    load_stage(0, 0);
    asm volatile("cp.async.commit_group;\n");

    for (int kt = 0; kt < 32; kt++) {
        const int cur = kt & 1;
        if (kt < 31) {
            load_stage(cur ^ 1, (kt + 1) * 32);
            asm volatile("cp.async.commit_group;\n");
            asm volatile("cp.async.wait_group 1;\n");
        } else {
            asm volatile("cp.async.wait_group 0;\n");
        }
        __syncthreads();

        const float* Asc = Asb[cur];
        const float* Bsc = Bsb[cur];
#pragma unroll
        for (int kk = 0; kk < 32; kk += 8) {
            wmma::fragment<wmma::matrix_a, 16, 16, 8, wmma::precision::tf32, wmma::row_major> af[4];
            wmma::fragment<wmma::matrix_b, 16, 16, 8, wmma::precision::tf32, wmma::row_major> bf[2];
#pragma unroll
            for (int i = 0; i < 4; i++)
                wmma::load_matrix_sync(af[i], &Asc[(wm * 64 + i * 16) * 36 + kk], 36);
#pragma unroll
            for (int j = 0; j < 2; j++)
                wmma::load_matrix_sync(bf[j], &Bsc[kk * 132 + wn * 32 + j * 16], 132);
#pragma unroll
            for (int i = 0; i < 4; i++)
#pragma unroll
                for (int j = 0; j < 2; j++)
                    wmma::mma_sync(acc[i][j], af[i], bf[j], acc[i][j]);
        }
        __syncthreads();
    }

#pragma unroll
    for (int i = 0; i < 4; i++)
#pragma unroll
        for (int j = 0; j < 2; j++)
            wmma::store_matrix_sync(&Cs[(wm * 64 + i * 16) * 132 + wn * 32 + j * 16],
                                    acc[i][j], 132, wmma::mem_row_major);
    __syncthreads();

    for (int idx = tid; idx < 128 * 128; idx += 256) {
        int r = idx >> 7, c = idx & 127;
        float val = Cs[r * 132 + c] + bias[bn + c];
        int m = bm + r, gc = bn + c;
        if (mode == 0) {
            int b_ = m >> 11, s = m & 2047;
            int h = gc / 192, rr = gc % 192;
            int which = rr >> 6, d = rr & 63;
            float* dst = (which == 0) ? g_q : (which == 1 ? g_k : g_v);
            dst[(((size_t)(b_ * NH + h)) * SEQ + s) * HD + d] = rtf32(val);
        } else {
            out[(size_t)m * 1024 + gc] = val;
        }
    }
}

// ---------------------------------------------------------------------------
// Causal flash attention. One block per (b, h, 128-row q-tile).
// 128 threads = 4 warps; warp wid owns q-rows [wid*32, wid*32+32).
// Each LANE owns one full q-row (64 cols): softmax fully lane-local (no
// shuffles), and K/V fragment smem traffic amortized over 32 rows per warp.
// smem: Qs 128x72 | Ks 64x72 | Vs 64x72 | Ps 128x72 = 110592 B (2 CTAs/SM)
// ---------------------------------------------------------------------------
__global__ __launch_bounds__(128) void attn_kernel(float* __restrict__ attn)
{
    extern __shared__ float sh[];
    float* Qs = sh;              // 9216
    float* Ks = sh + 9216;       // 4608
    float* Vs = sh + 13824;      // 4608
    float* Ps = sh + 18432;      // 9216

    const int bx = (int)blockIdx.x;
    const int qt = bx & 15;
    const int h = (bx >> 4) & 15;
    const int b = bx >> 8;
    const int tid = (int)threadIdx.x;
    const int wid = tid >> 5, lane = tid & 31;
    const size_t head_base = ((size_t)(b * NH + h)) * SEQ * HD;

    // Load Q tile (128x64), pre-scaled by 1/sqrt(D)=0.125 (exact pow2)
    {
        const float* qp = g_q + head_base + (size_t)qt * 128 * HD;
#pragma unroll
        for (int p = 0; p < 16; p++) {
            int lin = p * 128 + tid;
            int r = lin >> 4, c = (lin & 15) << 2;
            float4 t = *(const float4*)&qp[r * 64 + c];
            t.x *= 0.125f; t.y *= 0.125f; t.z *= 0.125f; t.w *= 0.125f;
            *(float4*)&Qs[r * 72 + c] = t;
        }
    }

    const int row_l = wid * 32 + lane;        // local q row (0..127)
    const int row_g = qt * 128 + row_l;       // global q row
    float* srow = &Ps[row_l * 72];

    float m_i = -INFINITY, l_i = 0.0f;
    float o[64];
#pragma unroll
    for (int i = 0; i < 64; i++) o[i] = 0.0f;

    const int njt = 2 * qt + 2;
    for (int j = 0; j < njt; j++) {
        __syncthreads();   // previous Ks/Vs fully consumed
        {
            const float* kp = g_k + head_base + (size_t)j * 64 * HD;
            const float* vp = g_v + head_base + (size_t)j * 64 * HD;
#pragma unroll
            for (int p = 0; p < 8; p++) {
                int lin = p * 128 + tid;
                int r = lin >> 4, c = (lin & 15) << 2;
                *(float4*)&Ks[r * 72 + c] = *(const float4*)&kp[r * 64 + c];
                *(float4*)&Vs[r * 72 + c] = *(const float4*)&vp[r * 64 + c];
            }
        }
        __syncthreads();

        // ---- S = (Q*scale) @ K^T for this warp's 32x64 strip ----
        {
            wmma::fragment<wmma::accumulator, 16, 16, 8, float> sf[2][4];
#pragma unroll
            for (int i = 0; i < 2; i++)
#pragma unroll
                for (int n = 0; n < 4; n++) wmma::fill_fragment(sf[i][n], 0.0f);
#pragma unroll
            for (int kk = 0; kk < 64; kk += 8) {
                wmma::fragment<wmma::matrix_a, 16, 16, 8, wmma::precision::tf32, wmma::row_major> af[2];
#pragma unroll
                for (int i = 0; i < 2; i++)
                    wmma::load_matrix_sync(af[i], &Qs[(wid * 32 + i * 16) * 72 + kk], 72);
#pragma unroll
                for (int n = 0; n < 4; n++) {
                    wmma::fragment<wmma::matrix_b, 16, 16, 8, wmma::precision::tf32, wmma::col_major> bf;
                    wmma::load_matrix_sync(bf, &Ks[(n * 16) * 72 + kk], 72);
#pragma unroll
                    for (int i = 0; i < 2; i++)
                        wmma::mma_sync(sf[i][n], af[i], bf, sf[i][n]);
                }
            }
#pragma unroll
            for (int i = 0; i < 2; i++)
#pragma unroll
                for (int n = 0; n < 4; n++)
                    wmma::store_matrix_sync(&Ps[(wid * 32 + i * 16) * 72 + n * 16],
                                            sf[i][n], 72, wmma::mem_row_major);
        }
        __syncwarp();

        // ---- online softmax: lane owns its whole row (no shuffles) ----
        float alpha;
        {
            const int colbase = j * 64;
            const int nvalid = row_g - colbase + 1;   // #unmasked cols (may be >64 or <=0)
            float rmax = -INFINITY;
#pragma unroll
            for (int c4 = 0; c4 < 16; c4++) {
                float4 t = *(float4*)&srow[c4 * 4];
                int cg = c4 * 4;
                if (cg + 0 < nvalid) rmax = fmaxf(rmax, t.x);
                if (cg + 1 < nvalid) rmax = fmaxf(rmax, t.y);
                if (cg + 2 < nvalid) rmax = fmaxf(rmax, t.z);
                if (cg + 3 < nvalid) rmax = fmaxf(rmax, t.w);
            }
            float m_new = fmaxf(m_i, rmax);
            alpha = __expf(m_i - m_new);   // 0 when m_i == -inf
            float lsum = 0.0f;
#pragma unroll
            for (int c4 = 0; c4 < 16; c4++) {
                float4 t = *(float4*)&srow[c4 * 4];
                int cg = c4 * 4;
                t.x = (cg + 0 < nvalid) ? __expf(t.x - m_new) : 0.0f;
                t.y = (cg + 1 < nvalid) ? __expf(t.y - m_new) : 0.0f;
                t.z = (cg + 2 < nvalid) ? __expf(t.z - m_new) : 0.0f;
                t.w = (cg + 3 < nvalid) ? __expf(t.w - m_new) : 0.0f;
                lsum += t.x + t.y + t.z + t.w;
                t.x = rtf32(t.x); t.y = rtf32(t.y);
                t.z = rtf32(t.z); t.w = rtf32(t.w);
                *(float4*)&srow[c4 * 4] = t;
            }
            l_i = alpha * l_i + lsum;
            m_i = m_new;
        }
        __syncwarp();

        // ---- T = P @ V for this warp's strip; result overwrites strip ----
        {
            wmma::fragment<wmma::accumulator, 16, 16, 8, float> tf[2][4];
#pragma unroll
            for (int i = 0; i < 2; i++)
#pragma unroll
                for (int n = 0; n < 4; n++) wmma::fill_fragment(tf[i][n], 0.0f);
#pragma unroll
            for (int kk = 0; kk < 64; kk += 8) {
                wmma::fragment<wmma::matrix_a, 16, 16, 8, wmma::precision::tf32, wmma::row_major> af[2];
#pragma unroll
                for (int i = 0; i < 2; i++)
                    wmma::load_matrix_sync(af[i], &Ps[(wid * 32 + i * 16) * 72 + kk], 72);
#pragma unroll
                for (int n = 0; n < 4; n++) {
                    wmma::fragment<wmma::matrix_b, 16, 16, 8, wmma::precision::tf32, wmma::row_major> bf;
                    wmma::load_matrix_sync(bf, &Vs[kk * 72 + n * 16], 72);
#pragma unroll
                    for (int i = 0; i < 2; i++)
                        wmma::mma_sync(tf[i][n], af[i], bf, tf[i][n]);
                }
            }
#pragma unroll
            for (int i = 0; i < 2; i++)
#pragma unroll
                for (int n = 0; n < 4; n++)
                    wmma::store_matrix_sync(&Ps[(wid * 32 + i * 16) * 72 + n * 16],
                                            tf[i][n], 72, wmma::mem_row_major);
        }
        __syncwarp();

        // ---- O update: o = o*alpha + T (lane-owned full row) ----
#pragma unroll
        for (int c4 = 0; c4 < 16; c4++) {
            float4 t = *(float4*)&srow[c4 * 4];
            o[c4*4+0] = o[c4*4+0] * alpha + t.x;
            o[c4*4+1] = o[c4*4+1] * alpha + t.y;
            o[c4*4+2] = o[c4*4+2] * alpha + t.z;
            o[c4*4+3] = o[c4*4+3] * alpha + t.w;
        }
    }

    // Normalize, round (GEMM2 consumes as tf32), scatter into reshape layout:
    // attn[b][h*128 + s/16][(s%16)*64 + d]  — d-run of 64 is contiguous
    const float inv_l = 1.0f / l_i;
    float* dst = attn + ((size_t)b * SEQ + h * 128 + (row_g >> 4)) * EMB
               + (size_t)(row_g & 15) * 64;
#pragma unroll
    for (int c4 = 0; c4 < 16; c4++) {
        float4 t;
        t.x = rtf32(o[c4*4+0] * inv_l);
        t.y = rtf32(o[c4*4+1] * inv_l);
        t.z = rtf32(o[c4*4+2] * inv_l);
        t.w = rtf32(o[c4*4+3] * inv_l);
        *(float4*)&dst[c4 * 4] = t;
    }
}

// ---------------------------------------------------------------------------
extern "C" void kernel_launch(void* const* d_in, const int* in_sizes, int n_in,
                              void* d_out, int out_size)
{
    (void)in_sizes; (void)n_in; (void)out_size;
    const float* x    = (const float*)d_in[0];
    // d_in[1] = causal mask (tril) — deterministic, hardcoded in attn_kernel
    const float* Wqkv = (const float*)d_in[2];
    const float* bqkv = (const float*)d_in[3];
    const float* Wo   = (const float*)d_in[4];
    const float* bo   = (const float*)d_in[5];
    float* out = (float*)d_out;

    static int init = 0;
    if (!init) {
        cudaFuncSetAttribute(gemm_tf32_kernel,
                             cudaFuncAttributeMaxDynamicSharedMemorySize, 70656);
        cudaFuncSetAttribute(attn_kernel,
                             cudaFuncAttributeMaxDynamicSharedMemorySize, 110592);
        init = 1;
    }

    float *attn_ptr, *xr_ptr, *wqkv_ptr, *wo_ptr;
    cudaGetSymbolAddress((void**)&attn_ptr, g_attn);
    cudaGetSymbolAddress((void**)&xr_ptr, g_xr);
    cudaGetSymbolAddress((void**)&wqkv_ptr, g_wqkv);
    cudaGetSymbolAddress((void**)&wo_ptr, g_wo);

    // 0) round inputs to nearest-tf32 once
    round_tf32_kernel<<<(2097152 + 255) / 256, 256>>>(x, xr_ptr, 2097152);
    round_tf32_kernel<<<(786432 + 255) / 256, 256>>>(Wqkv, wqkv_ptr, 786432);
    round_tf32_kernel<<<(262144 + 255) / 256, 256>>>(Wo, wo_ptr, 262144);

    // 1) QKV projection: [8192,1024] @ [1024,3072] + bqkv -> Q/K/V (rounded)
    gemm_tf32_kernel<<<dim3(24, 64), 256, 70656>>>(xr_ptr, wqkv_ptr, bqkv, 3072, 0, nullptr);

    // 2) Causal attention per (b, h, 128-row q-tile)
    attn_kernel<<<BB * NH * (SEQ / 128), 128, 110592>>>(attn_ptr);

    // 3) Output projection: [8192,1024] @ [1024,1024] + bo -> out
    gemm_tf32_kernel<<<dim3(8, 64), 256, 70656>>>(nullptr, wo_ptr, bo, 1024, 1, out);
}

// round 12
// speedup vs baseline: 2.8788x; 2.4994x over previous
#include <cuda_runtime.h>
#include <cuda_fp16.h>
#include <mma.h>
#include <math.h>

using namespace nvcuda;

#define BB 4
#define SEQ 2048
#define EMB 1024
#define NH 16
#define HD 64

// Scratch (device globals — no allocations allowed)
__device__ __half g_qh[BB * NH * SEQ * HD];
__device__ __half g_kh[BB * NH * SEQ * HD];
__device__ __half g_vh[BB * NH * SEQ * HD];
__device__ __half g_attnh[BB * SEQ * EMB];
__device__ __half g_xh[BB * SEQ * EMB];
__device__ __half g_wqkvh[EMB * 3 * EMB];
__device__ __half g_woh[EMB * EMB];

__device__ __forceinline__ void cp16(void* smem, const void* gmem) {
    unsigned a = (unsigned)__cvta_generic_to_shared(smem);
    asm volatile("cp.async.ca.shared.global [%0], [%1], 16;\n" :: "r"(a), "l"(gmem));
}

// ---------------------------------------------------------------------------
// fp32 -> fp16 pre-pass (4 elements per thread)
// ---------------------------------------------------------------------------
__global__ void to_half_kernel(const float* __restrict__ src,
                               __half* __restrict__ dst, int n4) {
    int i = blockIdx.x * blockDim.x + threadIdx.x;
    if (i < n4) {
        float4 t = ((const float4*)src)[i];
        __half2* d2 = (__half2*)dst;
        d2[2 * i + 0] = __floats2half2_rn(t.x, t.y);
        d2[2 * i + 1] = __floats2half2_rn(t.z, t.w);
    }
}

// ---------------------------------------------------------------------------
// FP16 GEMM, double-buffered cp.async: C[8192 x N] = A[8192x1024] @ B[1024xN] + bias
// BM=128, BN=128, BK=32, 256 threads, warp grid 2x4, warp tile 64x32 (4x2 frags)
// wmma m16n16k16, fp16 operands, fp32 accumulate.
//  mode 0: A = g_xh, B = g_wqkvh; epilogue adds bias, converts to half,
//          scatters into g_qh/g_kh/g_vh ([B,H,S,D])
//  mode 1: A = g_attnh, B = g_woh; epilogue writes out (fp32)
// smem: As[2] 128x40h (10240B ea), Bs[2] 32x136h (8704B ea) = 37888B;
//       Cs float 128x132 (67584B) reuses the whole arena after the mainloop.
// ---------------------------------------------------------------------------
__global__ __launch_bounds__(256, 2) void gemm_fp16_kernel(
    const __half* __restrict__ A, const __half* __restrict__ Bm,
    const float* __restrict__ bias, int N, int mode, float* __restrict__ out)
{
    extern __shared__ float sh[];
    __half* hbase = (__half*)sh;
    __half* Asb[2] = { hbase,         hbase + 5120 };   // 128 x 40 halves
    __half* Bsb[2] = { hbase + 10240, hbase + 14592 };  // 32 x 136 halves
    float* Cs = sh;                                     // 128 x 132 floats

    const int bm = blockIdx.y * 128;
    const int bn = blockIdx.x * 128;
    const int tid = (int)threadIdx.x;
    const int w = tid >> 5, wm = w >> 2, wn = w & 3;

    const __half* Aeff = (mode == 1) ? (const __half*)g_attnh : A;

    auto load_stage = [&](int st, int k0) {
        // A: 128x32 halves = 512 x 16B chunks -> 2 per thread
#pragma unroll
        for (int p = 0; p < 2; p++) {
            int idx = p * 256 + tid;
            int r = idx >> 2, c = (idx & 3) << 3;
            cp16(&Asb[st][r * 40 + c], &Aeff[(size_t)(bm + r) * 1024 + k0 + c]);
        }
        // B: 32x128 halves = 512 x 16B chunks -> 2 per thread
#pragma unroll
        for (int p = 0; p < 2; p++) {
            int idx = p * 256 + tid;
            int r = idx >> 4, c = (idx & 15) << 3;
            cp16(&Bsb[st][r * 136 + c], &Bm[(size_t)(k0 + r) * N + bn + c]);
        }
    };

    wmma::fragment<wmma::accumulator, 16, 16, 16, float> acc[4][2];
#pragma unroll
    for (int i = 0; i < 4; i++)
#pragma unroll
        for (int j = 0; j < 2; j++) wmma::fill_fragment(acc[i][j], 0.0f);

    load_stage(0, 0);
    asm volatile("cp.async.commit_group;\n");

    for (int kt = 0; kt < 32; kt++) {
        const int cur = kt & 1;
        if (kt < 31) {
            load_stage(cur ^ 1, (kt + 1) * 32);
            asm volatile("cp.async.commit_group;\n");
            asm volatile("cp.async.wait_group 1;\n");
        } else {
            asm volatile("cp.async.wait_group 0;\n");
        }
        __syncthreads();

        const __half* Asc = Asb[cur];
        const __half* Bsc = Bsb[cur];
#pragma unroll
        for (int kk = 0; kk < 32; kk += 16) {
            wmma::fragment<wmma::matrix_a, 16, 16, 16, __half, wmma::row_major> af[4];
            wmma::fragment<wmma::matrix_b, 16, 16, 16, __half, wmma::row_major> bf[2];
#pragma unroll
            for (int i = 0; i < 4; i++)
                wmma::load_matrix_sync(af[i], &Asc[(wm * 64 + i * 16) * 40 + kk], 40);
#pragma unroll
            for (int j = 0; j < 2; j++)
                wmma::load_matrix_sync(bf[j], &Bsc[kk * 136 + wn * 32 + j * 16], 136);
#pragma unroll
            for (int i = 0; i < 4; i++)
#pragma unroll
                for (int j = 0; j < 2; j++)
                    wmma::mma_sync(acc[i][j], af[i], bf[j], acc[i][j]);
        }
        __syncthreads();
    }

#pragma unroll
    for (int i = 0; i < 4; i++)
#pragma unroll
        for (int j = 0; j < 2; j++)
            wmma::store_matrix_sync(&Cs[(wm * 64 + i * 16) * 132 + wn * 32 + j * 16],
                                    acc[i][j], 132, wmma::mem_row_major);
    __syncthreads();

    // epilogue: 4 consecutive cols per thread
#pragma unroll
    for (int p = 0; p < 16; p++) {
        int idx = p * 256 + tid;
        int r = idx >> 5, c4 = (idx & 31) << 2;
        float4 t = *(float4*)&Cs[r * 132 + c4];
        float4 bb = *(const float4*)&bias[bn + c4];
        t.x += bb.x; t.y += bb.y; t.z += bb.z; t.w += bb.w;
        int m = bm + r, gc = bn + c4;
        if (mode == 0) {
            int b_ = m >> 11, s = m & 2047;
            int h = gc / 192, rr = gc % 192;
            int which = rr >> 6, d = rr & 63;
            __half* dst = (which == 0) ? g_qh : (which == 1 ? g_kh : g_vh);
            __half2* d2 = (__half2*)&dst[(((size_t)(b_ * NH + h)) * SEQ + s) * HD + d];
            d2[0] = __floats2half2_rn(t.x, t.y);
            d2[1] = __floats2half2_rn(t.z, t.w);
        } else {
            *(float4*)&out[(size_t)m * 1024 + gc] = t;
        }
    }
}

// ---------------------------------------------------------------------------
// Causal flash attention, fp16 operands / fp32 accum+softmax.
// One block per (b, h, 128-row q-tile); 128 threads = 4 warps; warp owns a
// 32-row strip; each LANE owns one full q-row (softmax shuffle-free).
// smem: Qs 128x72h | Ks 64x72h | Vs 64x72h | Ph 128x72h | Sf 128x68f = 90112B
// ---------------------------------------------------------------------------
__global__ __launch_bounds__(128) void attn_kernel(__half* __restrict__ attn)
{
    extern __shared__ char shb[];
    __half* Qs = (__half*)shb;                    // 18432B
    __half* Ks = (__half*)(shb + 18432);          //  9216B
    __half* Vs = (__half*)(shb + 27648);          //  9216B
    __half* Ph = (__half*)(shb + 36864);          // 18432B
    float*  Sf = (float*)(shb + 55296);           // 34816B (128 x 68)

    const int bx = (int)blockIdx.x;
    const int qt = bx & 15;
    const int h = (bx >> 4) & 15;
    const int b = bx >> 8;
    const int tid = (int)threadIdx.x;
    const int wid = tid >> 5, lane = tid & 31;
    const size_t head_base = ((size_t)(b * NH + h)) * SEQ * HD;

    // Load Q tile (128x64 h), scale by 0.125 (exact pow2 in fp16)
    {
        const __half* qp = g_qh + head_base + (size_t)qt * 128 * HD;
        const __half2 sc = __floats2half2_rn(0.125f, 0.125f);
#pragma unroll
        for (int p = 0; p < 8; p++) {
            int lin = p * 128 + tid;                  // 1024 chunks of 8 halves
            int r = lin >> 3, c = (lin & 7) << 3;
            __half2 v[4];
            *(uint4*)v = *(const uint4*)&qp[r * 64 + c];
            v[0] = __hmul2(v[0], sc); v[1] = __hmul2(v[1], sc);
            v[2] = __hmul2(v[2], sc); v[3] = __hmul2(v[3], sc);
            *(uint4*)&Qs[r * 72 + c] = *(uint4*)v;
        }
    }

    const int row_l = wid * 32 + lane;        // local q row (0..127)
    const int row_g = qt * 128 + row_l;       // global q row
    float* srow = &Sf[row_l * 68];
    __half* prow = &Ph[row_l * 72];

    float m_i = -INFINITY, l_i = 0.0f;
    float o[64];
#pragma unroll
    for (int i = 0; i < 64; i++) o[i] = 0.0f;

    const int njt = 2 * qt + 2;
    for (int j = 0; j < njt; j++) {
        __syncthreads();   // previous Ks/Vs fully consumed
        {
            const __half* kp = g_kh + head_base + (size_t)j * 64 * HD;
            const __half* vp = g_vh + head_base + (size_t)j * 64 * HD;
#pragma unroll
            for (int p = 0; p < 4; p++) {             // 512 chunks K + V
                int lin = p * 128 + tid;
                int r = lin >> 3, c = (lin & 7) << 3;
                *(uint4*)&Ks[r * 72 + c] = *(const uint4*)&kp[r * 64 + c];
                *(uint4*)&Vs[r * 72 + c] = *(const uint4*)&vp[r * 64 + c];
            }
        }
        __syncthreads();

        // ---- S = (Q*scale) @ K^T for this warp's 32x64 strip ----
        {
            wmma::fragment<wmma::accumulator, 16, 16, 16, float> sf[2][4];
#pragma unroll
            for (int i = 0; i < 2; i++)
#pragma unroll
                for (int n = 0; n < 4; n++) wmma::fill_fragment(sf[i][n], 0.0f);
#pragma unroll
            for (int kk = 0; kk < 64; kk += 16) {
                wmma::fragment<wmma::matrix_a, 16, 16, 16, __half, wmma::row_major> af[2];
#pragma unroll
                for (int i = 0; i < 2; i++)
                    wmma::load_matrix_sync(af[i], &Qs[(wid * 32 + i * 16) * 72 + kk], 72);
#pragma unroll
                for (int n = 0; n < 4; n++) {
                    wmma::fragment<wmma::matrix_b, 16, 16, 16, __half, wmma::col_major> bf;
                    wmma::load_matrix_sync(bf, &Ks[(n * 16) * 72 + kk], 72);
#pragma unroll
                    for (int i = 0; i < 2; i++)
                        wmma::mma_sync(sf[i][n], af[i], bf, sf[i][n]);
                }
            }
#pragma unroll
            for (int i = 0; i < 2; i++)
#pragma unroll
                for (int n = 0; n < 4; n++)
                    wmma::store_matrix_sync(&Sf[(wid * 32 + i * 16) * 68 + n * 16],
                                            sf[i][n], 68, wmma::mem_row_major);
        }
        __syncwarp();

        // ---- online softmax: lane owns its whole row ----
        float alpha;
        {
            const int nvalid = row_g - j * 64 + 1;
            float rmax = -INFINITY;
#pragma unroll
            for (int c4 = 0; c4 < 16; c4++) {
                float4 t = *(float4*)&srow[c4 * 4];
                int cg = c4 * 4;
                if (cg + 0 < nvalid) rmax = fmaxf(rmax, t.x);
                if (cg + 1 < nvalid) rmax = fmaxf(rmax, t.y);
                if (cg + 2 < nvalid) rmax = fmaxf(rmax, t.z);
                if (cg + 3 < nvalid) rmax = fmaxf(rmax, t.w);
            }
            float m_new = fmaxf(m_i, rmax);
            alpha = __expf(m_i - m_new);   // 0 when m_i == -inf
            float lsum = 0.0f;
#pragma unroll
            for (int c4 = 0; c4 < 16; c4++) {
                float4 t = *(float4*)&srow[c4 * 4];
                int cg = c4 * 4;
                t.x = (cg + 0 < nvalid) ? __expf(t.x - m_new) : 0.0f;
                t.y = (cg + 1 < nvalid) ? __expf(t.y - m_new) : 0.0f;
                t.z = (cg + 2 < nvalid) ? __expf(t.z - m_new) : 0.0f;
                t.w = (cg + 3 < nvalid) ? __expf(t.w - m_new) : 0.0f;
                lsum += t.x + t.y + t.z + t.w;
                __half2* p2 = (__half2*)&prow[c4 * 4];
                p2[0] = __floats2half2_rn(t.x, t.y);
                p2[1] = __floats2half2_rn(t.z, t.w);
            }
            l_i = alpha * l_i + lsum;
            m_i = m_new;
        }
        __syncwarp();

        // ---- T = P @ V for this warp's strip -> Sf ----
        {
            wmma::fragment<wmma::accumulator, 16, 16, 16, float> tf[2][4];
#pragma unroll
            for (int i = 0; i < 2; i++)
#pragma unroll
                for (int n = 0; n < 4; n++) wmma::fill_fragment(tf[i][n], 0.0f);
#pragma unroll
            for (int kk = 0; kk < 64; kk += 16) {
                wmma::fragment<wmma::matrix_a, 16, 16, 16, __half, wmma::row_major> af[2];
#pragma unroll
                for (int i = 0; i < 2; i++)
                    wmma::load_matrix_sync(af[i], &Ph[(wid * 32 + i * 16) * 72 + kk], 72);
#pragma unroll
                for (int n = 0; n < 4; n++) {
                    wmma::fragment<wmma::matrix_b, 16, 16, 16, __half, wmma::row_major> bf;
                    wmma::load_matrix_sync(bf, &Vs[kk * 72 + n * 16], 72);
#pragma unroll
                    for (int i = 0; i < 2; i++)
                        wmma::mma_sync(tf[i][n], af[i], bf, tf[i][n]);
                }
            }
#pragma unroll
            for (int i = 0; i < 2; i++)
#pragma unroll
                for (int n = 0; n < 4; n++)
                    wmma::store_matrix_sync(&Sf[(wid * 32 + i * 16) * 68 + n * 16],
                                            tf[i][n], 68, wmma::mem_row_major);
        }
        __syncwarp();

        // ---- O update: o = o*alpha + T (lane-owned full row) ----
#pragma unroll
        for (int c4 = 0; c4 < 16; c4++) {
            float4 t = *(float4*)&srow[c4 * 4];
            o[c4*4+0] = o[c4*4+0] * alpha + t.x;
            o[c4*4+1] = o[c4*4+1] * alpha + t.y;
            o[c4*4+2] = o[c4*4+2] * alpha + t.z;
            o[c4*4+3] = o[c4*4+3] * alpha + t.w;
        }
    }

    // Normalize, convert to half (GEMM2 operand), scatter into the reference's
    // "no-transpose reshape" layout: attn[b][h*128 + s/16][(s%16)*64 + d]
    const float inv_l = 1.0f / l_i;
    __half* dst = attn + ((size_t)b * SEQ + h * 128 + (row_g >> 4)) * EMB
                + (size_t)(row_g & 15) * 64;
#pragma unroll
    for (int c8 = 0; c8 < 8; c8++) {
        __half2 v[4];
        v[0] = __floats2half2_rn(o[c8*8+0] * inv_l, o[c8*8+1] * inv_l);
        v[1] = __floats2half2_rn(o[c8*8+2] * inv_l, o[c8*8+3] * inv_l);
        v[2] = __floats2half2_rn(o[c8*8+4] * inv_l, o[c8*8+5] * inv_l);
        v[3] = __floats2half2_rn(o[c8*8+6] * inv_l, o[c8*8+7] * inv_l);
        *(uint4*)&dst[c8 * 8] = *(uint4*)v;
    }
}

// ---------------------------------------------------------------------------
extern "C" void kernel_launch(void* const* d_in, const int* in_sizes, int n_in,
                              void* d_out, int out_size)
{
    (void)in_sizes; (void)n_in; (void)out_size;
    const float* x    = (const float*)d_in[0];
    // d_in[1] = causal mask (tril) — deterministic, hardcoded in attn_kernel
    const float* Wqkv = (const float*)d_in[2];
    const float* bqkv = (const float*)d_in[3];
    const float* Wo   = (const float*)d_in[4];
    const float* bo   = (const float*)d_in[5];
    float* out = (float*)d_out;

    static int init = 0;
    if (!init) {
        cudaFuncSetAttribute(gemm_fp16_kernel,
                             cudaFuncAttributeMaxDynamicSharedMemorySize, 67584);
        cudaFuncSetAttribute(attn_kernel,
                             cudaFuncAttributeMaxDynamicSharedMemorySize, 90112);
        init = 1;
    }

    __half *attn_ptr, *xh_ptr, *wqkvh_ptr, *woh_ptr;
    cudaGetSymbolAddress((void**)&attn_ptr, g_attnh);
    cudaGetSymbolAddress((void**)&xh_ptr, g_xh);
    cudaGetSymbolAddress((void**)&wqkvh_ptr, g_wqkvh);
    cudaGetSymbolAddress((void**)&woh_ptr, g_woh);

    // 0) convert inputs to fp16 once (same 11-bit significand as tf32)
    to_half_kernel<<<(2097152 + 255) / 256, 256>>>(x, xh_ptr, 2097152);
    to_half_kernel<<<(786432 + 255) / 256, 256>>>(Wqkv, wqkvh_ptr, 786432);
    to_half_kernel<<<(262144 + 255) / 256, 256>>>(Wo, woh_ptr, 262144);

    // 1) QKV projection: [8192,1024] @ [1024,3072] + bqkv -> Q/K/V (fp16)
    gemm_fp16_kernel<<<dim3(24, 64), 256, 67584>>>(xh_ptr, wqkvh_ptr, bqkv, 3072, 0, nullptr);

    // 2) Causal attention per (b, h, 128-row q-tile)
    attn_kernel<<<BB * NH * (SEQ / 128), 128, 90112>>>(attn_ptr);

    // 3) Output projection: [8192,1024] @ [1024,1024] + bo -> out (fp32)
    gemm_fp16_kernel<<<dim3(8, 64), 256, 67584>>>(nullptr, woh_ptr, bo, 1024, 1, out);
}

// round 15
// speedup vs baseline: 2.9079x; 1.0101x over previous
#include <cuda_runtime.h>
#include <cuda_fp16.h>
#include <mma.h>
#include <math.h>

using namespace nvcuda;

#define BB 4
#define SEQ 2048
#define EMB 1024
#define NH 16
#define HD 64

// Scratch (device globals — no allocations allowed)
__device__ __half g_qh[BB * NH * SEQ * HD];
__device__ __half g_kh[BB * NH * SEQ * HD];
__device__ __half g_vh[BB * NH * SEQ * HD];
__device__ __half g_attnh[BB * SEQ * EMB];
__device__ __half g_xh[BB * SEQ * EMB];
__device__ __half g_wqkvh[EMB * 3 * EMB];
__device__ __half g_woh[EMB * EMB];

__device__ __forceinline__ void cp16(void* smem, const void* gmem) {
    unsigned a = (unsigned)__cvta_generic_to_shared(smem);
    asm volatile("cp.async.ca.shared.global [%0], [%1], 16;\n" :: "r"(a), "l"(gmem));
}

// ---------------------------------------------------------------------------
// fp32 -> fp16 pre-pass (4 elements per thread)
// ---------------------------------------------------------------------------
__global__ void to_half_kernel(const float* __restrict__ src,
                               __half* __restrict__ dst, int n4) {
    int i = blockIdx.x * blockDim.x + threadIdx.x;
    if (i < n4) {
        float4 t = ((const float4*)src)[i];
        __half2* d2 = (__half2*)dst;
        d2[2 * i + 0] = __floats2half2_rn(t.x, t.y);
        d2[2 * i + 1] = __floats2half2_rn(t.z, t.w);
    }
}

// ---------------------------------------------------------------------------
// FP16 GEMM, double-buffered cp.async: C[8192 x N] = A[8192x1024] @ B[1024xN] + bias
// BM=128, BN=128, BK=64 (16 stages, 4 k-steps of 16 each), 256 threads,
// warp grid 2x4, warp tile 64x32 (4x2 frags). fp16 operands, fp32 accumulate.
//  mode 0: A = g_xh, B = g_wqkvh; epilogue scatters half Q/K/V ([B,H,S,D])
//  mode 1: A = g_attnh, B = g_woh; epilogue writes out (fp32)
// smem: As[2] 128x72h (18432B ea) | Bs[2] 64x136h (17408B ea) = 71680B
//       Cs float 128x132 (67584B) reuses the arena after the mainloop.
// ---------------------------------------------------------------------------
__global__ __launch_bounds__(256, 2) void gemm_fp16_kernel(
    const __half* __restrict__ A, const __half* __restrict__ Bm,
    const float* __restrict__ bias, int N, int mode, float* __restrict__ out)
{
    extern __shared__ float sh[];
    __half* hbase = (__half*)sh;
    __half* Asb[2] = { hbase,         hbase + 9216 };           // 128 x 72 halves
    __half* Bsb[2] = { hbase + 18432, hbase + 18432 + 8704 };   // 64 x 136 halves
    float* Cs = sh;                                             // 128 x 132 floats

    const int bm = blockIdx.y * 128;
    const int bn = blockIdx.x * 128;
    const int tid = (int)threadIdx.x;
    const int w = tid >> 5, wm = w >> 2, wn = w & 3;

    const __half* Aeff = (mode == 1) ? (const __half*)g_attnh : A;

    auto load_stage = [&](int st, int k0) {
        // A: 128x64 halves = 1024 x 16B chunks -> 4 per thread
#pragma unroll
        for (int p = 0; p < 4; p++) {
            int idx = p * 256 + tid;
            int r = idx >> 3, c = (idx & 7) << 3;
            cp16(&Asb[st][r * 72 + c], &Aeff[(size_t)(bm + r) * 1024 + k0 + c]);
        }
        // B: 64x128 halves = 1024 x 16B chunks -> 4 per thread
#pragma unroll
        for (int p = 0; p < 4; p++) {
            int idx = p * 256 + tid;
            int r = idx >> 4, c = (idx & 15) << 3;
            cp16(&Bsb[st][r * 136 + c], &Bm[(size_t)(k0 + r) * N + bn + c]);
        }
    };

    wmma::fragment<wmma::accumulator, 16, 16, 16, float> acc[4][2];
#pragma unroll
    for (int i = 0; i < 4; i++)
#pragma unroll
        for (int j = 0; j < 2; j++) wmma::fill_fragment(acc[i][j], 0.0f);

    load_stage(0, 0);
    asm volatile("cp.async.commit_group;\n");

    for (int kt = 0; kt < 16; kt++) {
        const int cur = kt & 1;
        if (kt < 15) {
            load_stage(cur ^ 1, (kt + 1) * 64);
            asm volatile("cp.async.commit_group;\n");
            asm volatile("cp.async.wait_group 1;\n");
        } else {
            asm volatile("cp.async.wait_group 0;\n");
        }
        __syncthreads();

        const __half* Asc = Asb[cur];
        const __half* Bsc = Bsb[cur];
#pragma unroll
        for (int kk = 0; kk < 64; kk += 16) {
            wmma::fragment<wmma::matrix_a, 16, 16, 16, __half, wmma::row_major> af[4];
            wmma::fragment<wmma::matrix_b, 16, 16, 16, __half, wmma::row_major> bf[2];
#pragma unroll
            for (int i = 0; i < 4; i++)
                wmma::load_matrix_sync(af[i], &Asc[(wm * 64 + i * 16) * 72 + kk], 72);
#pragma unroll
            for (int j = 0; j < 2; j++)
                wmma::load_matrix_sync(bf[j], &Bsc[kk * 136 + wn * 32 + j * 16], 136);
#pragma unroll
            for (int i = 0; i < 4; i++)
#pragma unroll
                for (int j = 0; j < 2; j++)
                    wmma::mma_sync(acc[i][j], af[i], bf[j], acc[i][j]);
        }
        __syncthreads();
    }

#pragma unroll
    for (int i = 0; i < 4; i++)
#pragma unroll
        for (int j = 0; j < 2; j++)
            wmma::store_matrix_sync(&Cs[(wm * 64 + i * 16) * 132 + wn * 32 + j * 16],
                                    acc[i][j], 132, wmma::mem_row_major);
    __syncthreads();

    // epilogue: 4 consecutive cols per thread
#pragma unroll
    for (int p = 0; p < 16; p++) {
        int idx = p * 256 + tid;
        int r = idx >> 5, c4 = (idx & 31) << 2;
        float4 t = *(float4*)&Cs[r * 132 + c4];
        float4 bb = *(const float4*)&bias[bn + c4];
        t.x += bb.x; t.y += bb.y; t.z += bb.z; t.w += bb.w;
        int m = bm + r, gc = bn + c4;
        if (mode == 0) {
            int b_ = m >> 11, s = m & 2047;
            int h = gc / 192, rr = gc % 192;
            int which = rr >> 6, d = rr & 63;
            __half* dst = (which == 0) ? g_qh : (which == 1 ? g_kh : g_vh);
            __half2* d2 = (__half2*)&dst[(((size_t)(b_ * NH + h)) * SEQ + s) * HD + d];
            d2[0] = __floats2half2_rn(t.x, t.y);
            d2[1] = __floats2half2_rn(t.z, t.w);
        } else {
            *(float4*)&out[(size_t)m * 1024 + gc] = t;
        }
    }
}

// ---------------------------------------------------------------------------
// Causal flash attention, fp16 operands / fp32 accum+softmax.
// One block per (b, h, 128-row q-tile); 128 threads = 4 warps; warp owns a
// 32-row strip; each LANE owns one full q-row (softmax shuffle-free).
// K/V tiles double-buffered via cp.async: next tile streams during compute.
// smem: Qs 128x72h | Ks[2] 64x72h | Vs[2] 64x72h | Ph 128x72h | Sf 128x68f
//     = 18432 + 18432 + 18432 + 18432 + 34816 = 108544 B (2 CTAs/SM)
// ---------------------------------------------------------------------------
__global__ __launch_bounds__(128) void attn_kernel(__half* __restrict__ attn)
{
    extern __shared__ char shb[];
    __half* Qs = (__half*)shb;                            // 18432B
    __half* Ksb[2] = { (__half*)(shb + 18432), (__half*)(shb + 27648) };
    __half* Vsb[2] = { (__half*)(shb + 36864), (__half*)(shb + 46080) };
    __half* Ph = (__half*)(shb + 55296);                  // 18432B
    float*  Sf = (float*)(shb + 73728);                   // 34816B (128 x 68)

    const int bx = (int)blockIdx.x;
    const int qt = bx & 15;
    const int h = (bx >> 4) & 15;
    const int b = bx >> 8;
    const int tid = (int)threadIdx.x;
    const int wid = tid >> 5, lane = tid & 31;
    const size_t head_base = ((size_t)(b * NH + h)) * SEQ * HD;

    // Load Q tile (128x64 h), scale by 0.125 (exact pow2 in fp16)
    {
        const __half* qp = g_qh + head_base + (size_t)qt * 128 * HD;
        const __half2 sc = __floats2half2_rn(0.125f, 0.125f);
#pragma unroll
        for (int p = 0; p < 8; p++) {
            int lin = p * 128 + tid;                  // 1024 chunks of 8 halves
            int r = lin >> 3, c = (lin & 7) << 3;
            __half2 v[4];
            *(uint4*)v = *(const uint4*)&qp[r * 64 + c];
            v[0] = __hmul2(v[0], sc); v[1] = __hmul2(v[1], sc);
            v[2] = __hmul2(v[2], sc); v[3] = __hmul2(v[3], sc);
            *(uint4*)&Qs[r * 72 + c] = *(uint4*)v;
        }
    }

    auto load_kv = [&](int st, int j) {
        const __half* kp = g_kh + head_base + (size_t)j * 64 * HD;
        const __half* vp = g_vh + head_base + (size_t)j * 64 * HD;
#pragma unroll
        for (int p = 0; p < 4; p++) {                 // 512 chunks K + 512 V
            int lin = p * 128 + tid;
            int r = lin >> 3, c = (lin & 7) << 3;
            cp16(&Ksb[st][r * 72 + c], &kp[r * 64 + c]);
            cp16(&Vsb[st][r * 72 + c], &vp[r * 64 + c]);
        }
    };

    const int row_l = wid * 32 + lane;        // local q row (0..127)
    const int row_g = qt * 128 + row_l;       // global q row
    float* srow = &Sf[row_l * 68];
    __half* prow = &Ph[row_l * 72];

    float m_i = -INFINITY, l_i = 0.0f;
    float o[64];
#pragma unroll
    for (int i = 0; i < 64; i++) o[i] = 0.0f;

    const int njt = 2 * qt + 2;

    load_kv(0, 0);
    asm volatile("cp.async.commit_group;\n");

    for (int j = 0; j < njt; j++) {
        const int cur = j & 1;
        if (j + 1 < njt) {
            load_kv(cur ^ 1, j + 1);
            asm volatile("cp.async.commit_group;\n");
            asm volatile("cp.async.wait_group 1;\n");
        } else {
            asm volatile("cp.async.wait_group 0;\n");
        }
        __syncthreads();

        const __half* Ks = Ksb[cur];
        const __half* Vs = Vsb[cur];

        // ---- S = (Q*scale) @ K^T for this warp's 32x64 strip ----
        {
            wmma::fragment<wmma::accumulator, 16, 16, 16, float> sf[2][4];
#pragma unroll
            for (int i = 0; i < 2; i++)
#pragma unroll
                for (int n = 0; n < 4; n++) wmma::fill_fragment(sf[i][n], 0.0f);
#pragma unroll
            for (int kk = 0; kk < 64; kk += 16) {
                wmma::fragment<wmma::matrix_a, 16, 16, 16, __half, wmma::row_major> af[2];
#pragma unroll
                for (int i = 0; i < 2; i++)
                    wmma::load_matrix_sync(af[i], &Qs[(wid * 32 + i * 16) * 72 + kk], 72);
#pragma unroll
                for (int n = 0; n < 4; n++) {
                    wmma::fragment<wmma::matrix_b, 16, 16, 16, __half, wmma::col_major> bf;
                    wmma::load_matrix_sync(bf, &Ks[(n * 16) * 72 + kk], 72);
#pragma unroll
                    for (int i = 0; i < 2; i++)
                        wmma::mma_sync(sf[i][n], af[i], bf, sf[i][n]);
                }
            }
#pragma unroll
            for (int i = 0; i < 2; i++)
#pragma unroll
                for (int n = 0; n < 4; n++)
                    wmma::store_matrix_sync(&Sf[(wid * 32 + i * 16) * 68 + n * 16],
                                            sf[i][n], 68, wmma::mem_row_major);
        }
        __syncwarp();

        // ---- online softmax: lane owns its whole row ----
        float alpha;
        {
            const int nvalid = row_g - j * 64 + 1;
            float rmax = -INFINITY;
#pragma unroll
            for (int c4 = 0; c4 < 16; c4++) {
                float4 t = *(float4*)&srow[c4 * 4];
                int cg = c4 * 4;
                if (cg + 0 < nvalid) rmax = fmaxf(rmax, t.x);
                if (cg + 1 < nvalid) rmax = fmaxf(rmax, t.y);
                if (cg + 2 < nvalid) rmax = fmaxf(rmax, t.z);
                if (cg + 3 < nvalid) rmax = fmaxf(rmax, t.w);
            }
            float m_new = fmaxf(m_i, rmax);
            alpha = __expf(m_i - m_new);   // 0 when m_i == -inf
            float lsum = 0.0f;
#pragma unroll
            for (int c4 = 0; c4 < 16; c4++) {
                float4 t = *(float4*)&srow[c4 * 4];
                int cg = c4 * 4;
                t.x = (cg + 0 < nvalid) ? __expf(t.x - m_new) : 0.0f;
                t.y = (cg + 1 < nvalid) ? __expf(t.y - m_new) : 0.0f;
                t.z = (cg + 2 < nvalid) ? __expf(t.z - m_new) : 0.0f;
                t.w = (cg + 3 < nvalid) ? __expf(t.w - m_new) : 0.0f;
                lsum += t.x + t.y + t.z + t.w;
                __half2* p2 = (__half2*)&prow[c4 * 4];
                p2[0] = __floats2half2_rn(t.x, t.y);
                p2[1] = __floats2half2_rn(t.z, t.w);
            }
            l_i = alpha * l_i + lsum;
            m_i = m_new;
        }
        __syncwarp();

        // ---- T = P @ V for this warp's strip -> Sf ----
        {
            wmma::fragment<wmma::accumulator, 16, 16, 16, float> tf[2][4];
#pragma unroll
            for (int i = 0; i < 2; i++)
#pragma unroll
                for (int n = 0; n < 4; n++) wmma::fill_fragment(tf[i][n], 0.0f);
#pragma unroll
            for (int kk = 0; kk < 64; kk += 16) {
                wmma::fragment<wmma::matrix_a, 16, 16, 16, __half, wmma::row_major> af[2];
#pragma unroll
                for (int i = 0; i < 2; i++)
                    wmma::load_matrix_sync(af[i], &Ph[(wid * 32 + i * 16) * 72 + kk], 72);
#pragma unroll
                for (int n = 0; n < 4; n++) {
                    wmma::fragment<wmma::matrix_b, 16, 16, 16, __half, wmma::row_major> bf;
                    wmma::load_matrix_sync(bf, &Vs[kk * 72 + n * 16], 72);
#pragma unroll
                    for (int i = 0; i < 2; i++)
                        wmma::mma_sync(tf[i][n], af[i], bf, tf[i][n]);
                }
            }
#pragma unroll
            for (int i = 0; i < 2; i++)
#pragma unroll
                for (int n = 0; n < 4; n++)
                    wmma::store_matrix_sync(&Sf[(wid * 32 + i * 16) * 68 + n * 16],
                                            tf[i][n], 68, wmma::mem_row_major);
        }
        __syncwarp();

        // ---- O update: o = o*alpha + T (lane-owned full row) ----
#pragma unroll
        for (int c4 = 0; c4 < 16; c4++) {
            float4 t = *(float4*)&srow[c4 * 4];
            o[c4*4+0] = o[c4*4+0] * alpha + t.x;
            o[c4*4+1] = o[c4*4+1] * alpha + t.y;
            o[c4*4+2] = o[c4*4+2] * alpha + t.z;
            o[c4*4+3] = o[c4*4+3] * alpha + t.w;
        }
        __syncthreads();   // all warps done with this KV buffer before reuse
    }

    // Normalize, convert to half (GEMM2 operand), scatter into the reference's
    // "no-transpose reshape" layout: attn[b][h*128 + s/16][(s%16)*64 + d]
    const float inv_l = 1.0f / l_i;
    __half* dst = attn + ((size_t)b * SEQ + h * 128 + (row_g >> 4)) * EMB
                + (size_t)(row_g & 15) * 64;
#pragma unroll
    for (int c8 = 0; c8 < 8; c8++) {
        __half2 v[4];
        v[0] = __floats2half2_rn(o[c8*8+0] * inv_l, o[c8*8+1] * inv_l);
        v[1] = __floats2half2_rn(o[c8*8+2] * inv_l, o[c8*8+3] * inv_l);
        v[2] = __floats2half2_rn(o[c8*8+4] * inv_l, o[c8*8+5] * inv_l);
        v[3] = __floats2half2_rn(o[c8*8+6] * inv_l, o[c8*8+7] * inv_l);
        *(uint4*)&dst[c8 * 8] = *(uint4*)v;
    }
}

// ---------------------------------------------------------------------------
extern "C" void kernel_launch(void* const* d_in, const int* in_sizes, int n_in,
                              void* d_out, int out_size)
{
    (void)in_sizes; (void)n_in; (void)out_size;
    const float* x    = (const float*)d_in[0];
    // d_in[1] = causal mask (tril) — deterministic, hardcoded in attn_kernel
    const float* Wqkv = (const float*)d_in[2];
    const float* bqkv = (const float*)d_in[3];
    const float* Wo   = (const float*)d_in[4];
    const float* bo   = (const float*)d_in[5];
    float* out = (float*)d_out;

    static int init = 0;
    if (!init) {
        cudaFuncSetAttribute(gemm_fp16_kernel,
                             cudaFuncAttributeMaxDynamicSharedMemorySize, 71680);
        cudaFuncSetAttribute(attn_kernel,
                             cudaFuncAttributeMaxDynamicSharedMemorySize, 108544);
        init = 1;
    }

    __half *attn_ptr, *xh_ptr, *wqkvh_ptr, *woh_ptr;
    cudaGetSymbolAddress((void**)&attn_ptr, g_attnh);
    cudaGetSymbolAddress((void**)&xh_ptr, g_xh);
    cudaGetSymbolAddress((void**)&wqkvh_ptr, g_wqkvh);
    cudaGetSymbolAddress((void**)&woh_ptr, g_woh);

    // 0) convert inputs to fp16 once (same 11-bit significand as tf32)
    to_half_kernel<<<(2097152 + 255) / 256, 256>>>(x, xh_ptr, 2097152);
    to_half_kernel<<<(786432 + 255) / 256, 256>>>(Wqkv, wqkvh_ptr, 786432);
    to_half_kernel<<<(262144 + 255) / 256, 256>>>(Wo, woh_ptr, 262144);

    // 1) QKV projection: [8192,1024] @ [1024,3072] + bqkv -> Q/K/V (fp16)
    gemm_fp16_kernel<<<dim3(24, 64), 256, 71680>>>(xh_ptr, wqkvh_ptr, bqkv, 3072, 0, nullptr);

    // 2) Causal attention per (b, h, 128-row q-tile)
    attn_kernel<<<BB * NH * (SEQ / 128), 128, 108544>>>(attn_ptr);

    // 3) Output projection: [8192,1024] @ [1024,1024] + bo -> out (fp32)
    gemm_fp16_kernel<<<dim3(8, 64), 256, 71680>>>(nullptr, woh_ptr, bo, 1024, 1, out);
}

// round 17
// speedup vs baseline: 4.3389x; 1.4921x over previous
#include <cuda_runtime.h>
#include <cuda_fp16.h>
#include <mma.h>
#include <math.h>

using namespace nvcuda;

#define BB 4
#define SEQ 2048
#define EMB 1024
#define NH 16
#define HD 64

// Scratch (device globals — no allocations allowed)
__device__ __half g_qh[BB * NH * SEQ * HD];
__device__ __half g_kh[BB * NH * SEQ * HD];
__device__ __half g_vh[BB * NH * SEQ * HD];
__device__ __half g_attnh[BB * SEQ * EMB];
__device__ __half g_xh[BB * SEQ * EMB];
__device__ __half g_wqkvh[EMB * 3 * EMB];
__device__ __half g_woh[EMB * EMB];

__device__ __forceinline__ void cp16(void* smem, const void* gmem) {
    unsigned a = (unsigned)__cvta_generic_to_shared(smem);
    asm volatile("cp.async.ca.shared.global [%0], [%1], 16;\n" :: "r"(a), "l"(gmem));
}
__device__ __forceinline__ void ldsm4(unsigned& r0, unsigned& r1, unsigned& r2,
                                      unsigned& r3, unsigned addr) {
    asm volatile("ldmatrix.sync.aligned.m8n8.x4.shared.b16 {%0,%1,%2,%3}, [%4];"
                 : "=r"(r0), "=r"(r1), "=r"(r2), "=r"(r3) : "r"(addr));
}
__device__ __forceinline__ void ldsm4t(unsigned& r0, unsigned& r1, unsigned& r2,
                                       unsigned& r3, unsigned addr) {
    asm volatile("ldmatrix.sync.aligned.m8n8.x4.trans.shared.b16 {%0,%1,%2,%3}, [%4];"
                 : "=r"(r0), "=r"(r1), "=r"(r2), "=r"(r3) : "r"(addr));
}
__device__ __forceinline__ void mma16816(float* c, const unsigned* a, const unsigned* b) {
    asm volatile(
        "mma.sync.aligned.m16n8k16.row.col.f32.f16.f16.f32 "
        "{%0,%1,%2,%3}, {%4,%5,%6,%7}, {%8,%9}, {%0,%1,%2,%3};"
        : "+f"(c[0]), "+f"(c[1]), "+f"(c[2]), "+f"(c[3])
        : "r"(a[0]), "r"(a[1]), "r"(a[2]), "r"(a[3]), "r"(b[0]), "r"(b[1]));
}
__device__ __forceinline__ unsigned f2h2(float lo, float hi) {
    __half2 t = __floats2half2_rn(lo, hi);
    return *reinterpret_cast<unsigned*>(&t);
}

// ---------------------------------------------------------------------------
// fp32 -> fp16 pre-pass
// ---------------------------------------------------------------------------
__global__ void to_half_kernel(const float* __restrict__ src,
                               __half* __restrict__ dst, int n4) {
    int i = blockIdx.x * blockDim.x + threadIdx.x;
    if (i < n4) {
        float4 t = ((const float4*)src)[i];
        __half2* d2 = (__half2*)dst;
        d2[2 * i + 0] = __floats2half2_rn(t.x, t.y);
        d2[2 * i + 1] = __floats2half2_rn(t.z, t.w);
    }
}

// ---------------------------------------------------------------------------
// FP16 GEMM (unchanged from R15): BM=128, BN=128, BK=64, 256 thr, 2 CTAs/SM
// ---------------------------------------------------------------------------
__global__ __launch_bounds__(256, 2) void gemm_fp16_kernel(
    const __half* __restrict__ A, const __half* __restrict__ Bm,
    const float* __restrict__ bias, int N, int mode, float* __restrict__ out)
{
    extern __shared__ float sh[];
    __half* hbase = (__half*)sh;
    __half* Asb[2] = { hbase,         hbase + 9216 };           // 128 x 72 halves
    __half* Bsb[2] = { hbase + 18432, hbase + 18432 + 8704 };   // 64 x 136 halves
    float* Cs = sh;                                             // 128 x 132 floats

    const int bm = blockIdx.y * 128;
    const int bn = blockIdx.x * 128;
    const int tid = (int)threadIdx.x;
    const int w = tid >> 5, wm = w >> 2, wn = w & 3;

    const __half* Aeff = (mode == 1) ? (const __half*)g_attnh : A;

    auto load_stage = [&](int st, int k0) {
#pragma unroll
        for (int p = 0; p < 4; p++) {
            int idx = p * 256 + tid;
            int r = idx >> 3, c = (idx & 7) << 3;
            cp16(&Asb[st][r * 72 + c], &Aeff[(size_t)(bm + r) * 1024 + k0 + c]);
        }
#pragma unroll
        for (int p = 0; p < 4; p++) {
            int idx = p * 256 + tid;
            int r = idx >> 4, c = (idx & 15) << 3;
            cp16(&Bsb[st][r * 136 + c], &Bm[(size_t)(k0 + r) * N + bn + c]);
        }
    };

    wmma::fragment<wmma::accumulator, 16, 16, 16, float> acc[4][2];
#pragma unroll
    for (int i = 0; i < 4; i++)
#pragma unroll
        for (int j = 0; j < 2; j++) wmma::fill_fragment(acc[i][j], 0.0f);

    load_stage(0, 0);
    asm volatile("cp.async.commit_group;\n");

    for (int kt = 0; kt < 16; kt++) {
        const int cur = kt & 1;
        if (kt < 15) {
            load_stage(cur ^ 1, (kt + 1) * 64);
            asm volatile("cp.async.commit_group;\n");
            asm volatile("cp.async.wait_group 1;\n");
        } else {
            asm volatile("cp.async.wait_group 0;\n");
        }
        __syncthreads();

        const __half* Asc = Asb[cur];
        const __half* Bsc = Bsb[cur];
#pragma unroll
        for (int kk = 0; kk < 64; kk += 16) {
            wmma::fragment<wmma::matrix_a, 16, 16, 16, __half, wmma::row_major> af[4];
            wmma::fragment<wmma::matrix_b, 16, 16, 16, __half, wmma::row_major> bf[2];
#pragma unroll
            for (int i = 0; i < 4; i++)
                wmma::load_matrix_sync(af[i], &Asc[(wm * 64 + i * 16) * 72 + kk], 72);
#pragma unroll
            for (int j = 0; j < 2; j++)
                wmma::load_matrix_sync(bf[j], &Bsc[kk * 136 + wn * 32 + j * 16], 136);
#pragma unroll
            for (int i = 0; i < 4; i++)
#pragma unroll
                for (int j = 0; j < 2; j++)
                    wmma::mma_sync(acc[i][j], af[i], bf[j], acc[i][j]);
        }
        __syncthreads();
    }

#pragma unroll
    for (int i = 0; i < 4; i++)
#pragma unroll
        for (int j = 0; j < 2; j++)
            wmma::store_matrix_sync(&Cs[(wm * 64 + i * 16) * 132 + wn * 32 + j * 16],
                                    acc[i][j], 132, wmma::mem_row_major);
    __syncthreads();

#pragma unroll
    for (int p = 0; p < 16; p++) {
        int idx = p * 256 + tid;
        int r = idx >> 5, c4 = (idx & 31) << 2;
        float4 t = *(float4*)&Cs[r * 132 + c4];
        float4 bb = *(const float4*)&bias[bn + c4];
        t.x += bb.x; t.y += bb.y; t.z += bb.z; t.w += bb.w;
        int m = bm + r, gc = bn + c4;
        if (mode == 0) {
            int b_ = m >> 11, s = m & 2047;
            int h = gc / 192, rr = gc % 192;
            int which = rr >> 6, d = rr & 63;
            __half* dst = (which == 0) ? g_qh : (which == 1 ? g_kh : g_vh);
            __half2* d2 = (__half2*)&dst[(((size_t)(b_ * NH + h)) * SEQ + s) * HD + d];
            d2[0] = __floats2half2_rn(t.x, t.y);
            d2[1] = __floats2half2_rn(t.z, t.w);
        } else {
            *(float4*)&out[(size_t)m * 1024 + gc] = t;
        }
    }
}

// ---------------------------------------------------------------------------
// Causal flash attention, register-resident FA-2 (raw mma.m16n8k16).
// One block per (b, h, 128-row q-tile); 128 threads = 4 warps; warp owns a
// 32x64 strip: 2 m-tiles x 8 n-tiles of m16n8k16. S stays in accumulators;
// softmax on fragments (quad shfl); P packed to fp16 in regs (C-layout of two
// adjacent n-tiles == A-frag layout); O accumulated in regs across KV loop.
// K read via ldmatrix (non-trans), V via ldmatrix.trans. KV double-buffered.
// smem: Qs 128x72h | Ks[2] 64x72h | Vs[2] 64x72h = 55296 B
// ---------------------------------------------------------------------------
__global__ __launch_bounds__(128) void attn_kernel(__half* __restrict__ attn)
{
    extern __shared__ char shb[];
    __half* Qs = (__half*)shb;                            // 18432B
    __half* Ksb[2] = { (__half*)(shb + 18432), (__half*)(shb + 27648) };
    __half* Vsb[2] = { (__half*)(shb + 36864), (__half*)(shb + 46080) };

    const int bx = (int)blockIdx.x;
    const int qt = bx & 15;
    const int h = (bx >> 4) & 15;
    const int b = bx >> 8;
    const int tid = (int)threadIdx.x;
    const int wid = tid >> 5, lane = tid & 31;
    const size_t head_base = ((size_t)(b * NH + h)) * SEQ * HD;

    // Load Q tile (128x64 h), scale by 0.125 (exact pow2 in fp16)
    {
        const __half* qp = g_qh + head_base + (size_t)qt * 128 * HD;
        const __half2 sc = __floats2half2_rn(0.125f, 0.125f);
#pragma unroll
        for (int p = 0; p < 8; p++) {
            int lin = p * 128 + tid;
            int r = lin >> 3, c = (lin & 7) << 3;
            __half2 v[4];
            *(uint4*)v = *(const uint4*)&qp[r * 64 + c];
            v[0] = __hmul2(v[0], sc); v[1] = __hmul2(v[1], sc);
            v[2] = __hmul2(v[2], sc); v[3] = __hmul2(v[3], sc);
            *(uint4*)&Qs[r * 72 + c] = *(uint4*)v;
        }
    }

    auto load_kv = [&](int st, int j) {
        const __half* kp = g_kh + head_base + (size_t)j * 64 * HD;
        const __half* vp = g_vh + head_base + (size_t)j * 64 * HD;
#pragma unroll
        for (int p = 0; p < 4; p++) {
            int lin = p * 128 + tid;
            int r = lin >> 3, c = (lin & 7) << 3;
            cp16(&Ksb[st][r * 72 + c], &kp[r * 64 + c]);
            cp16(&Vsb[st][r * 72 + c], &vp[r * 64 + c]);
        }
    };

    const int njt = 2 * qt + 2;
    load_kv(0, 0);
    asm volatile("cp.async.commit_group;\n");
    __syncthreads();   // Qs visible to all warps

    // Preload Q A-fragments: qa[m][kg], m16k16 each
    unsigned qa[2][4][4];
    {
        unsigned qbase = (unsigned)__cvta_generic_to_shared(Qs);
#pragma unroll
        for (int m = 0; m < 2; m++)
#pragma unroll
            for (int kg = 0; kg < 4; kg++) {
                unsigned addr = qbase + (unsigned)((wid * 32 + m * 16 + (lane & 15)) * 144
                              + kg * 32 + ((lane >> 4) & 1) * 16);
                ldsm4(qa[m][kg][0], qa[m][kg][1], qa[m][kg][2], qa[m][kg][3], addr);
            }
    }

    float o[2][8][4];
#pragma unroll
    for (int m = 0; m < 2; m++)
#pragma unroll
        for (int n = 0; n < 8; n++)
#pragma unroll
            for (int e = 0; e < 4; e++) o[m][n][e] = 0.0f;
    float mM[4] = { -INFINITY, -INFINITY, -INFINITY, -INFINITY };
    float lL[4] = { 0.0f, 0.0f, 0.0f, 0.0f };

    const int rbase = qt * 128 + wid * 32;

    for (int j = 0; j < njt; j++) {
        const int cur = j & 1;
        if (j + 1 < njt) {
            load_kv(cur ^ 1, j + 1);
            asm volatile("cp.async.commit_group;\n");
            asm volatile("cp.async.wait_group 1;\n");
        } else {
            asm volatile("cp.async.wait_group 0;\n");
        }
        __syncthreads();

        // warps entirely above the diagonal for this KV tile skip it
        if (j * 64 <= rbase + 31) {
            unsigned kbase = (unsigned)__cvta_generic_to_shared(Ksb[cur]);
            unsigned vbase = (unsigned)__cvta_generic_to_shared(Vsb[cur]);

            // ---- S = Q @ K^T (2x8 m16n8 accum tiles) ----
            float sf[2][8][4];
#pragma unroll
            for (int m = 0; m < 2; m++)
#pragma unroll
                for (int n = 0; n < 8; n++)
#pragma unroll
                    for (int e = 0; e < 4; e++) sf[m][n][e] = 0.0f;

#pragma unroll
            for (int kg = 0; kg < 4; kg++) {
                unsigned kb[8][2];
#pragma unroll
                for (int np = 0; np < 4; np++) {
                    unsigned addr = kbase
                        + (unsigned)((np * 16 + (lane & 7) + ((lane >> 4) & 1) * 8) * 144
                        + kg * 32 + ((lane >> 3) & 1) * 16);
                    unsigned r0, r1, r2, r3;
                    ldsm4(r0, r1, r2, r3, addr);
                    kb[2 * np][0] = r0; kb[2 * np][1] = r1;
                    kb[2 * np + 1][0] = r2; kb[2 * np + 1][1] = r3;
                }
#pragma unroll
                for (int m = 0; m < 2; m++)
#pragma unroll
                    for (int n = 0; n < 8; n++)
                        mma16816(sf[m][n], qa[m][kg], kb[n]);
            }

            // ---- causal mask (only tiles touching the diagonal) ----
            if (j * 64 + 63 > rbase) {
#pragma unroll
                for (int m = 0; m < 2; m++)
#pragma unroll
                    for (int n = 0; n < 8; n++)
#pragma unroll
                        for (int e = 0; e < 4; e++) {
                            int col = j * 64 + n * 8 + 2 * (lane & 3) + (e & 1);
                            int row = rbase + m * 16 + (lane >> 2) + (e >> 1) * 8;
                            if (col > row) sf[m][n][e] = -INFINITY;
                        }
            }

            // ---- online softmax on fragments (quad-reduce) ----
            float alpha[4];
#pragma unroll
            for (int m = 0; m < 2; m++)
#pragma unroll
                for (int hh = 0; hh < 2; hh++) {
                    int si = 2 * m + hh;
                    float tmax = -INFINITY;
#pragma unroll
                    for (int n = 0; n < 8; n++)
                        tmax = fmaxf(tmax, fmaxf(sf[m][n][2 * hh], sf[m][n][2 * hh + 1]));
                    tmax = fmaxf(tmax, __shfl_xor_sync(0xffffffffu, tmax, 1));
                    tmax = fmaxf(tmax, __shfl_xor_sync(0xffffffffu, tmax, 2));
                    float mnew = fmaxf(mM[si], tmax);
                    alpha[si] = __expf(mM[si] - mnew);   // 0 when mM == -inf
                    float ls = 0.0f;
#pragma unroll
                    for (int n = 0; n < 8; n++) {
                        float p0 = __expf(sf[m][n][2 * hh] - mnew);
                        float p1 = __expf(sf[m][n][2 * hh + 1] - mnew);
                        sf[m][n][2 * hh] = p0; sf[m][n][2 * hh + 1] = p1;
                        ls += p0 + p1;
                    }
                    ls += __shfl_xor_sync(0xffffffffu, ls, 1);
                    ls += __shfl_xor_sync(0xffffffffu, ls, 2);
                    lL[si] = alpha[si] * lL[si] + ls;
                    mM[si] = mnew;
                }

            // ---- scale O by alpha (per-row, elementwise on fragments) ----
#pragma unroll
            for (int m = 0; m < 2; m++)
#pragma unroll
                for (int n = 0; n < 8; n++) {
                    o[m][n][0] *= alpha[2 * m];     o[m][n][1] *= alpha[2 * m];
                    o[m][n][2] *= alpha[2 * m + 1]; o[m][n][3] *= alpha[2 * m + 1];
                }

            // ---- pack P to fp16 A-frags in registers ----
            unsigned pa[2][4][4];
#pragma unroll
            for (int m = 0; m < 2; m++)
#pragma unroll
                for (int kg = 0; kg < 4; kg++) {
                    pa[m][kg][0] = f2h2(sf[m][2 * kg][0], sf[m][2 * kg][1]);
                    pa[m][kg][1] = f2h2(sf[m][2 * kg][2], sf[m][2 * kg][3]);
                    pa[m][kg][2] = f2h2(sf[m][2 * kg + 1][0], sf[m][2 * kg + 1][1]);
                    pa[m][kg][3] = f2h2(sf[m][2 * kg + 1][2], sf[m][2 * kg + 1][3]);
                }

            // ---- O += P @ V ----
#pragma unroll
            for (int kg = 0; kg < 4; kg++) {
                unsigned vb[8][2];
#pragma unroll
                for (int np = 0; np < 4; np++) {
                    unsigned addr = vbase
                        + (unsigned)((kg * 16 + (lane & 7) + ((lane >> 3) & 1) * 8) * 144
                        + np * 32 + ((lane >> 4) & 1) * 16);
                    unsigned r0, r1, r2, r3;
                    ldsm4t(r0, r1, r2, r3, addr);
                    vb[2 * np][0] = r0; vb[2 * np][1] = r1;
                    vb[2 * np + 1][0] = r2; vb[2 * np + 1][1] = r3;
                }
#pragma unroll
                for (int m = 0; m < 2; m++)
#pragma unroll
                    for (int n = 0; n < 8; n++)
                        mma16816(o[m][n], pa[m][kg], vb[n]);
            }
        }
        __syncthreads();   // all warps done with this KV buffer before reuse
    }

    // ---- normalize + store into the reference's reshape layout ----
#pragma unroll
    for (int m = 0; m < 2; m++) {
        float inv0 = 1.0f / lL[2 * m];
        float inv1 = 1.0f / lL[2 * m + 1];
        int rlo = rbase + m * 16 + (lane >> 2);
        int rhi = rlo + 8;
        __half* dlo = attn + ((size_t)b * SEQ + h * 128 + (rlo >> 4)) * EMB
                    + (size_t)(rlo & 15) * 64;
        __half* dhi = attn + ((size_t)b * SEQ + h * 128 + (rhi >> 4)) * EMB
                    + (size_t)(rhi & 15) * 64;
#pragma unroll
        for (int n = 0; n < 8; n++) {
            int d = n * 8 + 2 * (lane & 3);
            *(__half2*)&dlo[d] = __floats2half2_rn(o[m][n][0] * inv0, o[m][n][1] * inv0);
            *(__half2*)&dhi[d] = __floats2half2_rn(o[m][n][2] * inv1, o[m][n][3] * inv1);
        }
    }
}

// ---------------------------------------------------------------------------
extern "C" void kernel_launch(void* const* d_in, const int* in_sizes, int n_in,
                              void* d_out, int out_size)
{
    (void)in_sizes; (void)n_in; (void)out_size;
    const float* x    = (const float*)d_in[0];
    // d_in[1] = causal mask (tril) — deterministic, hardcoded in attn_kernel
    const float* Wqkv = (const float*)d_in[2];
    const float* bqkv = (const float*)d_in[3];
    const float* Wo   = (const float*)d_in[4];
    const float* bo   = (const float*)d_in[5];
    float* out = (float*)d_out;

    static int init = 0;
    if (!init) {
        cudaFuncSetAttribute(gemm_fp16_kernel,
                             cudaFuncAttributeMaxDynamicSharedMemorySize, 71680);
        cudaFuncSetAttribute(attn_kernel,
                             cudaFuncAttributeMaxDynamicSharedMemorySize, 55296);
        init = 1;
    }

    __half *attn_ptr, *xh_ptr, *wqkvh_ptr, *woh_ptr;
    cudaGetSymbolAddress((void**)&attn_ptr, g_attnh);
    cudaGetSymbolAddress((void**)&xh_ptr, g_xh);
    cudaGetSymbolAddress((void**)&wqkvh_ptr, g_wqkvh);
    cudaGetSymbolAddress((void**)&woh_ptr, g_woh);

    // 0) convert inputs to fp16 once
    to_half_kernel<<<(2097152 + 255) / 256, 256>>>(x, xh_ptr, 2097152);
    to_half_kernel<<<(786432 + 255) / 256, 256>>>(Wqkv, wqkvh_ptr, 786432);
    to_half_kernel<<<(262144 + 255) / 256, 256>>>(Wo, woh_ptr, 262144);

    // 1) QKV projection: [8192,1024] @ [1024,3072] + bqkv -> Q/K/V (fp16)
    gemm_fp16_kernel<<<dim3(24, 64), 256, 71680>>>(xh_ptr, wqkvh_ptr, bqkv, 3072, 0, nullptr);

    // 2) Causal attention per (b, h, 128-row q-tile)
    attn_kernel<<<BB * NH * (SEQ / 128), 128, 55296>>>(attn_ptr);

    // 3) Output projection: [8192,1024] @ [1024,1024] + bo -> out (fp32)
    gemm_fp16_kernel<<<dim3(8, 64), 256, 71680>>>(nullptr, woh_ptr, bo, 1024, 1, out);
}